// round 9
// baseline (speedup 1.0000x reference)
#include <cuda_runtime.h>
#include <cuda_bf16.h>
#include <math.h>
#include <stdint.h>

#define NNODES 32768
#define NBATCH 16
#define NS 2048
#define HID 64
#define ETOT 524288
#define TM 128
#define EPSF 1e-5f

// ---------------- scratch ----------------
__device__ float g_h[NNODES * HID];
__device__ float g_agg[NNODES * HID];
__device__ float g_u[NNODES * HID];
__device__ float g_X[NNODES * 3];
__device__ float g_Y[64 * 3];
__device__ float g_acc[2 * NBATCH];

// ---------------- smem: weights only (tile-invariant) ----------------
// B1 = W1^T [64 n][136 k pad] bf16 (272B/row); B2 = W2^T [64][72] (144B/row)
#define B1_HI  0
#define B1_LO  17408
#define B2_HI  34816
#define B2_LO  44032
#define BIAS1  53248
#define BIAS2  53504
#define SMEM_MMA_BYTES 53760

static __device__ __forceinline__ uint32_t cvta_smem(const void* p) {
    uint32_t a;
    asm("{ .reg .u64 t; cvta.to.shared.u64 t, %1; cvt.u32.u64 %0, t; }" : "=r"(a) : "l"(p));
    return a;
}
static __device__ __forceinline__ void ldsm4(uint32_t* r, uint32_t addr) {
    asm volatile("ldmatrix.sync.aligned.m8n8.x4.shared.b16 {%0,%1,%2,%3}, [%4];"
                 : "=r"(r[0]), "=r"(r[1]), "=r"(r[2]), "=r"(r[3]) : "r"(addr));
}
static __device__ __forceinline__ void mma_bf16(float* c, const uint32_t* a, const uint32_t* b) {
    asm volatile(
        "mma.sync.aligned.m16n8k16.row.col.f32.bf16.bf16.f32 "
        "{%0,%1,%2,%3}, {%4,%5,%6,%7}, {%8,%9}, {%0,%1,%2,%3};"
        : "+f"(c[0]), "+f"(c[1]), "+f"(c[2]), "+f"(c[3])
        : "r"(a[0]), "r"(a[1]), "r"(a[2]), "r"(a[3]), "r"(b[0]), "r"(b[1]));
}
// pack two floats into bf16x2 hi + lo correction words
static __device__ __forceinline__ void split2(float x, float y, uint32_t& hi, uint32_t& lo) {
    __nv_bfloat16 hx = __float2bfloat16(x), hy = __float2bfloat16(y);
    __nv_bfloat16 lx = __float2bfloat16(x - __bfloat162float(hx));
    __nv_bfloat16 ly = __float2bfloat16(y - __bfloat162float(hy));
    hi = ((uint32_t)__bfloat16_as_ushort(hy) << 16) | (uint32_t)__bfloat16_as_ushort(hx);
    lo = ((uint32_t)__bfloat16_as_ushort(ly) << 16) | (uint32_t)__bfloat16_as_ushort(lx);
}

// fast exp, FFMA-only
__device__ __forceinline__ float fexp(float x) {
    const float L2E = 1.4426950408889634f;
    float t = fmaf(x, L2E, 12582912.0f);
    float kf = t - 12582912.0f;
    float f = fmaf(x, L2E, -kf);
    float p = 1.33335581e-3f;
    p = fmaf(p, f, 9.61812911e-3f);
    p = fmaf(p, f, 5.55041087e-2f);
    p = fmaf(p, f, 2.40226507e-1f);
    p = fmaf(p, f, 6.93147181e-1f);
    p = fmaf(p, f, 1.0f);
    int ik = (int)kf;
    return __int_as_float(__float_as_int(p) + (ik << 23));
}

__global__ void compute_Y_kernel() {
    int i = threadIdx.x;
    if (i < 64) {
        double phi = 3.14159265358979323846 * (3.0 - sqrt(5.0));
        double y = 1.0 - 2.0 * (double)i / 63.0;
        double r = sqrt(fmax(0.0, 1.0 - y * y));
        double th = phi * (double)i;
        g_Y[i * 3 + 0] = (float)(cos(th) * r);
        g_Y[i * 3 + 1] = (float)y;
        g_Y[i * 3 + 2] = (float)(sin(th) * r);
    }
}

__global__ void zero_agg_kernel() {
    int i = blockIdx.x * blockDim.x + threadIdx.x;
    reinterpret_cast<float4*>(g_agg)[i] = make_float4(0.f, 0.f, 0.f, 0.f);
}

__global__ void zero_acc_kernel() {
    int i = threadIdx.x;
    if (i < 2 * NBATCH) g_acc[i] = 0.f;
}

__global__ void encoder_kernel(const float* __restrict__ x,
                               const float* __restrict__ W,
                               const float* __restrict__ b) {
    __shared__ float sW[3 * HID];
    __shared__ float sb[HID];
    int t = threadIdx.x;
    if (t < 3 * HID) sW[t] = W[t];
    if (t < HID) sb[t] = b[t];
    __syncthreads();
    int idx = blockIdx.x * 256 + t;
    int n = idx >> 6, c = idx & 63;
    float x0 = x[n * 3 + 0], x1 = x[n * 3 + 1], x2 = x[n * 3 + 2];
    g_h[idx] = fmaf(x0, sW[c], fmaf(x1, sW[HID + c], fmaf(x2, sW[2 * HID + c], sb[c])));
}

// ============ register-resident back-to-back warp-MMA MLP ============
// 128 threads (4 warps), warp = m32 x n64, TM=128 rows/tile, 2 CTAs/SM.
// No per-tile __syncthreads.
template <bool EDGE>
__global__ void __launch_bounds__(128, 2) mlp_mma_kernel(
    const float* __restrict__ W1g, const float* __restrict__ b1g,
    const float* __restrict__ W2g, const float* __restrict__ b2g,
    const int* __restrict__ esrc, const int* __restrict__ edst) {
    extern __shared__ char sp[];
    const uint32_t sb = cvta_smem(sp);
    const int t = threadIdx.x, lane = t & 31, wid = t >> 5;

    float* b1v = reinterpret_cast<float*>(sp + BIAS1);
    float* b2v = reinterpret_cast<float*>(sp + BIAS2);

    // ---- load tile-invariant weights (once) ----
    for (int i = t; i < 128 * 64; i += 128) {
        int k = i >> 6, n = i & 63;
        float w = W1g[i];
        __nv_bfloat16 hi = __float2bfloat16(w);
        __nv_bfloat16 lo = __float2bfloat16(w - __bfloat162float(hi));
        reinterpret_cast<__nv_bfloat16*>(sp + B1_HI)[n * 136 + k] = hi;
        reinterpret_cast<__nv_bfloat16*>(sp + B1_LO)[n * 136 + k] = lo;
    }
    for (int i = t; i < 64 * 64; i += 128) {
        int k = i >> 6, n = i & 63;
        float w = W2g[i];
        __nv_bfloat16 hi = __float2bfloat16(w);
        __nv_bfloat16 lo = __float2bfloat16(w - __bfloat162float(hi));
        reinterpret_cast<__nv_bfloat16*>(sp + B2_HI)[n * 72 + k] = hi;
        reinterpret_cast<__nv_bfloat16*>(sp + B2_LO)[n * 72 + k] = lo;
    }
    if (t < 64) { b1v[t] = b1g[t]; b2v[t] = b2g[t]; }
    __syncthreads();      // the ONLY barrier

    const int g = lane >> 3;
    const int b_row = (g >> 1) * 8 + (lane & 7);
    const int b_koff = (g & 1) * 8;
    const int er = lane >> 2, ec = lane & 3;
    const int m0 = wid * 32;

    const uint32_t aB1 = sb + B1_HI + (uint32_t)b_row * 272 + b_koff * 2;
    const uint32_t aB2 = sb + B2_HI + (uint32_t)b_row * 144 + b_koff * 2;

    const int ntiles = (EDGE ? ETOT : NNODES) / TM;
    for (int tile = blockIdx.x; tile < ntiles; tile += gridDim.x) {
        const int base = tile * TM;
        // rows owned by this thread: rr[0..3] = er, er+8 (mt0) ; er+16, er+24 (mt1)
        int rr[4], dd[4];
        const float *rowD[4], *rowS[4];
        #pragma unroll
        for (int i = 0; i < 4; i++) rr[i] = base + m0 + 8 * i + er;
        if (EDGE) {
            #pragma unroll
            for (int i = 0; i < 4; i++) {
                dd[i] = edst[rr[i]];
                int s = esrc[rr[i]];
                rowD[i] = g_h + (size_t)dd[i] * HID;
                rowS[i] = g_h + (size_t)s * HID;
            }
        } else {
            #pragma unroll
            for (int i = 0; i < 4; i++) {
                rowD[i] = g_h + (size_t)rr[i] * HID;
                rowS[i] = g_agg + (size_t)rr[i] * HID;
            }
        }

        // ---- GEMM1: acc1[2 mt][8 nt] = A[m32 x k128] @ B1^T, 3-term split ----
        float acc1[2][8][4];
        #pragma unroll
        for (int mt = 0; mt < 2; mt++)
            #pragma unroll
            for (int nt = 0; nt < 8; nt++)
                #pragma unroll
                for (int j = 0; j < 4; j++) acc1[mt][nt][j] = 0.f;
        #pragma unroll
        for (int kk = 0; kk < 8; kk++) {
            const int kb = (kk & 3) * 16;
            uint32_t ah[2][4], al[2][4];
            #pragma unroll
            for (int mt = 0; mt < 2; mt++) {
                const float* qa = (kk < 4) ? rowD[2 * mt] : rowS[2 * mt];
                const float* qb = (kk < 4) ? rowD[2 * mt + 1] : rowS[2 * mt + 1];
                float2 p0 = *reinterpret_cast<const float2*>(qa + kb + 2 * ec);
                float2 p1 = *reinterpret_cast<const float2*>(qb + kb + 2 * ec);
                float2 p2 = *reinterpret_cast<const float2*>(qa + kb + 8 + 2 * ec);
                float2 p3 = *reinterpret_cast<const float2*>(qb + kb + 8 + 2 * ec);
                split2(p0.x, p0.y, ah[mt][0], al[mt][0]);
                split2(p1.x, p1.y, ah[mt][1], al[mt][1]);
                split2(p2.x, p2.y, ah[mt][2], al[mt][2]);
                split2(p3.x, p3.y, ah[mt][3], al[mt][3]);
            }
            uint32_t bh[4][4], bl[4][4];
            #pragma unroll
            for (int i = 0; i < 4; i++) {
                uint32_t a = aB1 + (uint32_t)i * 16 * 272 + kk * 32;
                ldsm4(bh[i], a);
                ldsm4(bl[i], a + 17408);
            }
            #pragma unroll
            for (int mt = 0; mt < 2; mt++)
                #pragma unroll
                for (int nt = 0; nt < 8; nt++) {
                    const uint32_t* bhp = &bh[nt >> 1][(nt & 1) * 2];
                    const uint32_t* blp = &bl[nt >> 1][(nt & 1) * 2];
                    mma_bf16(acc1[mt][nt], ah[mt], bhp);
                    mma_bf16(acc1[mt][nt], al[mt], bhp);
                    mma_bf16(acc1[mt][nt], ah[mt], blp);
                }
        }
        // ---- convert: bias+relu, C-frags -> A-frags of GEMM2 (registers only) ----
        uint32_t fh[2][4][4], fl[2][4][4];
        #pragma unroll
        for (int mt = 0; mt < 2; mt++)
            #pragma unroll
            for (int j = 0; j < 4; j++) {
                float2 ba = *reinterpret_cast<const float2*>(b1v + 16 * j + 2 * ec);
                float2 bb = *reinterpret_cast<const float2*>(b1v + 16 * j + 8 + 2 * ec);
                float v00 = fmaxf(acc1[mt][2 * j][0] + ba.x, 0.f);
                float v01 = fmaxf(acc1[mt][2 * j][1] + ba.y, 0.f);
                float v10 = fmaxf(acc1[mt][2 * j][2] + ba.x, 0.f);
                float v11 = fmaxf(acc1[mt][2 * j][3] + ba.y, 0.f);
                float w00 = fmaxf(acc1[mt][2 * j + 1][0] + bb.x, 0.f);
                float w01 = fmaxf(acc1[mt][2 * j + 1][1] + bb.y, 0.f);
                float w10 = fmaxf(acc1[mt][2 * j + 1][2] + bb.x, 0.f);
                float w11 = fmaxf(acc1[mt][2 * j + 1][3] + bb.y, 0.f);
                split2(v00, v01, fh[mt][j][0], fl[mt][j][0]);
                split2(v10, v11, fh[mt][j][1], fl[mt][j][1]);
                split2(w00, w01, fh[mt][j][2], fl[mt][j][2]);
                split2(w10, w11, fh[mt][j][3], fl[mt][j][3]);
            }
        // ---- GEMM2: acc2[2 mt][8 nt] = Mid[m32 x k64] @ B2^T ----
        float acc2[2][8][4];
        #pragma unroll
        for (int mt = 0; mt < 2; mt++)
            #pragma unroll
            for (int nt = 0; nt < 8; nt++)
                #pragma unroll
                for (int j = 0; j < 4; j++) acc2[mt][nt][j] = 0.f;
        #pragma unroll
        for (int kk = 0; kk < 4; kk++) {
            uint32_t bh[4][4], bl[4][4];
            #pragma unroll
            for (int i = 0; i < 4; i++) {
                uint32_t a = aB2 + (uint32_t)i * 16 * 144 + kk * 32;
                ldsm4(bh[i], a);
                ldsm4(bl[i], a + 9216);
            }
            #pragma unroll
            for (int mt = 0; mt < 2; mt++)
                #pragma unroll
                for (int nt = 0; nt < 8; nt++) {
                    const uint32_t* bhp = &bh[nt >> 1][(nt & 1) * 2];
                    const uint32_t* blp = &bl[nt >> 1][(nt & 1) * 2];
                    mma_bf16(acc2[mt][nt], fh[mt][kk], bhp);
                    mma_bf16(acc2[mt][nt], fl[mt][kk], bhp);
                    mma_bf16(acc2[mt][nt], fh[mt][kk], blp);
                }
        }
        // ---- epilogue: bias+relu -> scatter/store ----
        #pragma unroll
        for (int mt = 0; mt < 2; mt++)
            #pragma unroll
            for (int nt = 0; nt < 8; nt++) {
                int n = 8 * nt + 2 * ec;
                float2 bb = *reinterpret_cast<const float2*>(b2v + n);
                float v00 = fmaxf(acc2[mt][nt][0] + bb.x, 0.f);
                float v01 = fmaxf(acc2[mt][nt][1] + bb.y, 0.f);
                float v10 = fmaxf(acc2[mt][nt][2] + bb.x, 0.f);
                float v11 = fmaxf(acc2[mt][nt][3] + bb.y, 0.f);
                if (EDGE) {
                    float* p0 = g_agg + (size_t)dd[2 * mt] * HID + n;
                    float* p1 = g_agg + (size_t)dd[2 * mt + 1] * HID + n;
                    asm volatile("red.global.add.v2.f32 [%0], {%1,%2};"
                                 :: "l"(p0), "f"(v00), "f"(v01) : "memory");
                    asm volatile("red.global.add.v2.f32 [%0], {%1,%2};"
                                 :: "l"(p1), "f"(v10), "f"(v11) : "memory");
                } else {
                    *reinterpret_cast<float2*>(g_u + (size_t)rr[2 * mt] * HID + n) =
                        make_float2(v00, v01);
                    *reinterpret_cast<float2*>(g_u + (size_t)rr[2 * mt + 1] * HID + n) =
                        make_float2(v10, v11);
                }
            }
    }
}

// ---------------- InstanceNorm: 64 blocks = (graph, 16-ch quad) ----------------
__global__ void instnorm_kernel() {
    int g = blockIdx.x >> 2, cq = (blockIdx.x & 3) << 4;
    int t = threadIdx.x;          // 512
    int c = t & 15, r = t >> 4;   // r 0..31
    const float* basep = g_u + (size_t)g * NS * HID + cq + c;
    float* outp = g_h + (size_t)g * NS * HID + cq + c;
    __shared__ float red[32][16];
    float s = 0.f;
    for (int n = r; n < NS; n += 32) s += basep[(size_t)n * HID];
    red[r][c] = s;
    __syncthreads();
    if (r == 0) {
        float tot = 0.f;
        #pragma unroll
        for (int i = 0; i < 32; i++) tot += red[i][c];
        red[0][c] = tot * (1.0f / NS);
    }
    __syncthreads();
    float mean = red[0][c];
    __syncthreads();
    float s2 = 0.f;
    for (int n = r; n < NS; n += 32) {
        float d = basep[(size_t)n * HID] - mean;
        s2 = fmaf(d, d, s2);
    }
    red[r][c] = s2;
    __syncthreads();
    if (r == 0) {
        float tot = 0.f;
        #pragma unroll
        for (int i = 0; i < 32; i++) tot += red[i][c];
        red[0][c] = rsqrtf(tot * (1.0f / NS) + EPSF);
    }
    __syncthreads();
    float inv = red[0][c];
    for (int n = r; n < NS; n += 32)
        outp[(size_t)n * HID] = (basep[(size_t)n * HID] - mean) * inv;
}

// ---------------- decoder ----------------
__global__ void decoder_kernel(const float* __restrict__ W, const float* __restrict__ b,
                               float* __restrict__ out) {
    __shared__ float sW[HID * 3];
    __shared__ float sb[3];
    int t = threadIdx.x;
    if (t < HID * 3) sW[t] = W[t];
    if (t < 3) sb[t] = b[t];
    __syncthreads();
    int n = blockIdx.x * 256 + t;
    float a0 = sb[0], a1 = sb[1], a2 = sb[2];
    const float* hr = g_h + (size_t)n * HID;
    #pragma unroll 8
    for (int k = 0; k < HID; k++) {
        float v = hr[k];
        a0 = fmaf(v, sW[k * 3 + 0], a0);
        a1 = fmaf(v, sW[k * 3 + 1], a1);
        a2 = fmaf(v, sW[k * 3 + 2], a2);
    }
    float inv = rsqrtf(a0 * a0 + a1 * a1 + a2 * a2);
    a0 *= inv; a1 *= inv; a2 *= inv;
    g_X[n * 3 + 0] = a0; g_X[n * 3 + 1] = a1; g_X[n * 3 + 2] = a2;
    out[1 + n * 3 + 0] = a0; out[1 + n * 3 + 1] = a1; out[1 + n * 3 + 2] = a2;
}

// ---------------- MMD kernels ----------------
__global__ void kxx_kernel() {
    int bid = blockIdx.x;
    int g = bid >> 8, tm = (bid >> 4) & 15, tn = bid & 15;
    const float* Xg = g_X + (size_t)g * NS * 3;
    __shared__ float ax[128][4];
    __shared__ float ay[128][4];
    __shared__ float rs[256];
    int t = threadIdx.x;
    for (int i = t; i < 128 * 3; i += 256) {
        int row = i / 3, col = i - row * 3;
        ax[row][col] = Xg[tm * 128 * 3 + i];
        ay[row][col] = Xg[tn * 128 * 3 + i];
    }
    __syncthreads();
    int r0 = (t >> 4) << 3, cb = (t & 15) << 3;
    float yv[8][3];
    #pragma unroll
    for (int j = 0; j < 8; j++) {
        yv[j][0] = ay[cb + j][0]; yv[j][1] = ay[cb + j][1]; yv[j][2] = ay[cb + j][2];
    }
    float s = 0.f;
    #pragma unroll
    for (int i = 0; i < 8; i++) {
        float x0 = ax[r0 + i][0], x1 = ax[r0 + i][1], x2 = ax[r0 + i][2];
        #pragma unroll
        for (int j = 0; j < 8; j++) {
            float d = fmaf(x0, yv[j][0], fmaf(x1, yv[j][1], x2 * yv[j][2]));
            s += fexp(fmaf(2.f, d, -2.f));
        }
    }
    rs[t] = s;
    __syncthreads();
    for (int o = 128; o > 0; o >>= 1) { if (t < o) rs[t] += rs[t + o]; __syncthreads(); }
    if (t == 0) atomicAdd(&g_acc[g], rs[0]);
}

__global__ void kxy_kernel() {
    __shared__ float sy[64][4];
    __shared__ float rs[256];
    int t = threadIdx.x;
    int n = blockIdx.x * 256 + t;
    for (int i = t; i < 64 * 3; i += 256) { int row = i / 3; sy[row][i - row * 3] = g_Y[i]; }
    __syncthreads();
    float x0 = g_X[n * 3], x1 = g_X[n * 3 + 1], x2 = g_X[n * 3 + 2];
    float s = 0.f;
    #pragma unroll 8
    for (int j = 0; j < 64; j++) {
        float d = fmaf(x0, sy[j][0], fmaf(x1, sy[j][1], x2 * sy[j][2]));
        s += fexp(fmaf(2.f, d, -2.f));
    }
    rs[t] = s;
    __syncthreads();
    for (int o = 128; o > 0; o >>= 1) { if (t < o) rs[t] += rs[t + o]; __syncthreads(); }
    if (t == 0) atomicAdd(&g_acc[NBATCH + (n >> 11)], rs[0]);
}

__global__ void finalize_kernel(float* __restrict__ out) {
    __shared__ float rs[64];
    int t = threadIdx.x;
    float x0 = g_Y[t * 3], x1 = g_Y[t * 3 + 1], x2 = g_Y[t * 3 + 2];
    float s = 0.f;
    for (int j = 0; j < 64; j++) {
        float d = fmaf(x0, g_Y[j * 3], fmaf(x1, g_Y[j * 3 + 1], x2 * g_Y[j * 3 + 2]));
        s += fexp(fmaf(2.f, d, -2.f));
    }
    rs[t] = s;
    __syncthreads();
    if (t == 0) {
        float kyy = 0.f;
        for (int j = 0; j < 64; j++) kyy += rs[j];
        kyy *= (1.0f / (64.f * 64.f));
        float loss = 0.f;
        for (int b = 0; b < NBATCH; b++) {
            float kxx = g_acc[b] * (1.0f / ((float)NS * (float)NS));
            float kxy = g_acc[NBATCH + b] * (1.0f / ((float)NS * 64.f));
            loss += kxx - 2.f * kxy + kyy;
        }
        out[0] = loss * (1.0f / NBATCH);
    }
}

// ---------------- launch ----------------
extern "C" void kernel_launch(void* const* d_in, const int* in_sizes, int n_in,
                              void* d_out, int out_size) {
    const float* x    = (const float*)d_in[0];
    const int*   esrc = (const int*)d_in[1];
    const int*   edst = (const int*)d_in[2];
    const float* encW = (const float*)d_in[4];
    const float* encb = (const float*)d_in[5];
    const float* m1W  = (const float*)d_in[6];
    const float* m1b  = (const float*)d_in[7];
    const float* m2W  = (const float*)d_in[8];
    const float* m2b  = (const float*)d_in[9];
    const float* u1W  = (const float*)d_in[10];
    const float* u1b  = (const float*)d_in[11];
    const float* u2W  = (const float*)d_in[12];
    const float* u2b  = (const float*)d_in[13];
    const float* decW = (const float*)d_in[14];
    const float* decb = (const float*)d_in[15];
    float* out = (float*)d_out;

    cudaFuncSetAttribute((const void*)mlp_mma_kernel<true>,
                         cudaFuncAttributeMaxDynamicSharedMemorySize, SMEM_MMA_BYTES);
    cudaFuncSetAttribute((const void*)mlp_mma_kernel<false>,
                         cudaFuncAttributeMaxDynamicSharedMemorySize, SMEM_MMA_BYTES);

    compute_Y_kernel<<<1, 64>>>();
    encoder_kernel<<<NNODES * HID / 256, 256>>>(x, encW, encb);

    for (int l = 0; l < 4; l++) {
        zero_agg_kernel<<<NNODES * HID / 1024, 256>>>();
        mlp_mma_kernel<true><<<296, 128, SMEM_MMA_BYTES>>>(
            m1W + (size_t)l * 128 * 64, m1b + (size_t)l * 64,
            m2W + (size_t)l * 64 * 64,  m2b + (size_t)l * 64, esrc, edst);
        mlp_mma_kernel<false><<<256, 128, SMEM_MMA_BYTES>>>(
            u1W + (size_t)l * 128 * 64, u1b + (size_t)l * 64,
            u2W + (size_t)l * 64 * 64,  u2b + (size_t)l * 64, nullptr, nullptr);
        instnorm_kernel<<<64, 512>>>();
    }

    zero_acc_kernel<<<1, 32>>>();
    decoder_kernel<<<NNODES / 256, 256>>>(decW, decb, out);
    kxy_kernel<<<NNODES / 256, 256>>>();
    kxx_kernel<<<NBATCH * 16 * 16, 256>>>();
    finalize_kernel<<<1, 64>>>(out);
}

// round 12
// speedup vs baseline: 1.0324x; 1.0324x over previous
#include <cuda_runtime.h>
#include <cuda_bf16.h>
#include <math.h>
#include <stdint.h>

#define NNODES 32768
#define NBATCH 16
#define NS 2048
#define HID 64
#define ETOT 524288
#define TM 128
#define EPSF 1e-5f

// ---------------- scratch ----------------
__device__ float g_h[NNODES * HID];
__device__ float g_agg[NNODES * HID];
__device__ float g_u[NNODES * HID];
__device__ float g_X[NNODES * 3];
__device__ float g_Y[64 * 3];
__device__ float g_acc[2 * NBATCH];

// ---------------- smem: weights only (tile-invariant) ----------------
// B1 = W1^T [64 n][136 k pad] bf16 (272B/row); B2 = W2^T [64][72] (144B/row)
#define B1_HI  0
#define B1_LO  17408
#define B2_HI  34816
#define B2_LO  44032
#define BIAS1  53248
#define BIAS2  53504
#define SMEM_MMA_BYTES 53760

static __device__ __forceinline__ uint32_t cvta_smem(const void* p) {
    uint32_t a;
    asm("{ .reg .u64 t; cvta.to.shared.u64 t, %1; cvt.u32.u64 %0, t; }" : "=r"(a) : "l"(p));
    return a;
}
static __device__ __forceinline__ void ldsm4(uint32_t* r, uint32_t addr) {
    asm volatile("ldmatrix.sync.aligned.m8n8.x4.shared.b16 {%0,%1,%2,%3}, [%4];"
                 : "=r"(r[0]), "=r"(r[1]), "=r"(r[2]), "=r"(r[3]) : "r"(addr));
}
static __device__ __forceinline__ void mma_bf16(float* c, const uint32_t* a, const uint32_t* b) {
    asm volatile(
        "mma.sync.aligned.m16n8k16.row.col.f32.bf16.bf16.f32 "
        "{%0,%1,%2,%3}, {%4,%5,%6,%7}, {%8,%9}, {%0,%1,%2,%3};"
        : "+f"(c[0]), "+f"(c[1]), "+f"(c[2]), "+f"(c[3])
        : "r"(a[0]), "r"(a[1]), "r"(a[2]), "r"(a[3]), "r"(b[0]), "r"(b[1]));
}
// pack two floats into bf16x2 hi + lo correction words
static __device__ __forceinline__ void split2(float x, float y, uint32_t& hi, uint32_t& lo) {
    __nv_bfloat16 hx = __float2bfloat16(x), hy = __float2bfloat16(y);
    __nv_bfloat16 lx = __float2bfloat16(x - __bfloat162float(hx));
    __nv_bfloat16 ly = __float2bfloat16(y - __bfloat162float(hy));
    hi = ((uint32_t)__bfloat16_as_ushort(hy) << 16) | (uint32_t)__bfloat16_as_ushort(hx);
    lo = ((uint32_t)__bfloat16_as_ushort(ly) << 16) | (uint32_t)__bfloat16_as_ushort(lx);
}

// fast exp, FFMA-only
__device__ __forceinline__ float fexp(float x) {
    const float L2E = 1.4426950408889634f;
    float t = fmaf(x, L2E, 12582912.0f);
    float kf = t - 12582912.0f;
    float f = fmaf(x, L2E, -kf);
    float p = 1.33335581e-3f;
    p = fmaf(p, f, 9.61812911e-3f);
    p = fmaf(p, f, 5.55041087e-2f);
    p = fmaf(p, f, 2.40226507e-1f);
    p = fmaf(p, f, 6.93147181e-1f);
    p = fmaf(p, f, 1.0f);
    int ik = (int)kf;
    return __int_as_float(__float_as_int(p) + (ik << 23));
}

__global__ void compute_Y_kernel() {
    int i = threadIdx.x;
    if (i < 64) {
        double phi = 3.14159265358979323846 * (3.0 - sqrt(5.0));
        double y = 1.0 - 2.0 * (double)i / 63.0;
        double r = sqrt(fmax(0.0, 1.0 - y * y));
        double th = phi * (double)i;
        g_Y[i * 3 + 0] = (float)(cos(th) * r);
        g_Y[i * 3 + 1] = (float)y;
        g_Y[i * 3 + 2] = (float)(sin(th) * r);
    }
}

__global__ void zero_agg_kernel() {
    int i = blockIdx.x * blockDim.x + threadIdx.x;
    reinterpret_cast<float4*>(g_agg)[i] = make_float4(0.f, 0.f, 0.f, 0.f);
}

__global__ void zero_acc_kernel() {
    int i = threadIdx.x;
    if (i < 2 * NBATCH) g_acc[i] = 0.f;
}

__global__ void encoder_kernel(const float* __restrict__ x,
                               const float* __restrict__ W,
                               const float* __restrict__ b) {
    __shared__ float sW[3 * HID];
    __shared__ float sb[HID];
    int t = threadIdx.x;
    if (t < 3 * HID) sW[t] = W[t];
    if (t < HID) sb[t] = b[t];
    __syncthreads();
    int idx = blockIdx.x * 256 + t;
    int n = idx >> 6, c = idx & 63;
    float x0 = x[n * 3 + 0], x1 = x[n * 3 + 1], x2 = x[n * 3 + 2];
    g_h[idx] = fmaf(x0, sW[c], fmaf(x1, sW[HID + c], fmaf(x2, sW[2 * HID + c], sb[c])));
}

// ============ register-resident back-to-back warp-MMA MLP ============
// 128 threads (4 warps), warp = m32 x n64, TM=128 rows/tile, 3 CTAs/SM.
// No per-tile __syncthreads.
template <bool EDGE>
__global__ void __launch_bounds__(128, 3) mlp_mma_kernel(
    const float* __restrict__ W1g, const float* __restrict__ b1g,
    const float* __restrict__ W2g, const float* __restrict__ b2g,
    const int* __restrict__ esrc, const int* __restrict__ edst) {
    extern __shared__ char sp[];
    const uint32_t sb = cvta_smem(sp);
    const int t = threadIdx.x, lane = t & 31, wid = t >> 5;

    float* b1v = reinterpret_cast<float*>(sp + BIAS1);
    float* b2v = reinterpret_cast<float*>(sp + BIAS2);

    // ---- load tile-invariant weights (once) ----
    for (int i = t; i < 128 * 64; i += 128) {
        int k = i >> 6, n = i & 63;
        float w = W1g[i];
        __nv_bfloat16 hi = __float2bfloat16(w);
        __nv_bfloat16 lo = __float2bfloat16(w - __bfloat162float(hi));
        reinterpret_cast<__nv_bfloat16*>(sp + B1_HI)[n * 136 + k] = hi;
        reinterpret_cast<__nv_bfloat16*>(sp + B1_LO)[n * 136 + k] = lo;
    }
    for (int i = t; i < 64 * 64; i += 128) {
        int k = i >> 6, n = i & 63;
        float w = W2g[i];
        __nv_bfloat16 hi = __float2bfloat16(w);
        __nv_bfloat16 lo = __float2bfloat16(w - __bfloat162float(hi));
        reinterpret_cast<__nv_bfloat16*>(sp + B2_HI)[n * 72 + k] = hi;
        reinterpret_cast<__nv_bfloat16*>(sp + B2_LO)[n * 72 + k] = lo;
    }
    if (t < 64) { b1v[t] = b1g[t]; b2v[t] = b2g[t]; }
    __syncthreads();      // the ONLY barrier

    const int g = lane >> 3;
    const int b_row = (g >> 1) * 8 + (lane & 7);
    const int b_koff = (g & 1) * 8;
    const int er = lane >> 2, ec = lane & 3;
    const int m0 = wid * 32;

    const uint32_t aB1 = sb + B1_HI + (uint32_t)b_row * 272 + b_koff * 2;
    const uint32_t aB2 = sb + B2_HI + (uint32_t)b_row * 144 + b_koff * 2;

    const int ntiles = (EDGE ? ETOT : NNODES) / TM;
    for (int tile = blockIdx.x; tile < ntiles; tile += gridDim.x) {
        const int base = tile * TM;
        // rows owned by this thread: rr[i] = base + m0 + 8i + er, i=0..3
        int dd[4], ss[4];
        #pragma unroll
        for (int i = 0; i < 4; i++) {
            int r = base + m0 + 8 * i + er;
            if (EDGE) { dd[i] = edst[r]; ss[i] = esrc[r]; }
            else      { dd[i] = r;        ss[i] = r; }
        }

        // ---- GEMM1: acc1[2 mt][8 nt] = A[m32 x k128] @ B1^T, 3-term split ----
        float acc1[2][8][4];
        #pragma unroll
        for (int mt = 0; mt < 2; mt++)
            #pragma unroll
            for (int nt = 0; nt < 8; nt++)
                #pragma unroll
                for (int j = 0; j < 4; j++) acc1[mt][nt][j] = 0.f;
        #pragma unroll
        for (int kk = 0; kk < 8; kk++) {
            const int kb = (kk & 3) * 16;
            uint32_t ah[2][4], al[2][4];
            #pragma unroll
            for (int mt = 0; mt < 2; mt++) {
                const float* qa;
                const float* qb;
                if (kk < 4) {
                    qa = g_h + (size_t)dd[2 * mt] * HID;
                    qb = g_h + (size_t)dd[2 * mt + 1] * HID;
                } else {
                    qa = (EDGE ? g_h : g_agg) + (size_t)ss[2 * mt] * HID;
                    qb = (EDGE ? g_h : g_agg) + (size_t)ss[2 * mt + 1] * HID;
                }
                float2 p0 = *reinterpret_cast<const float2*>(qa + kb + 2 * ec);
                float2 p1 = *reinterpret_cast<const float2*>(qb + kb + 2 * ec);
                float2 p2 = *reinterpret_cast<const float2*>(qa + kb + 8 + 2 * ec);
                float2 p3 = *reinterpret_cast<const float2*>(qb + kb + 8 + 2 * ec);
                split2(p0.x, p0.y, ah[mt][0], al[mt][0]);
                split2(p1.x, p1.y, ah[mt][1], al[mt][1]);
                split2(p2.x, p2.y, ah[mt][2], al[mt][2]);
                split2(p3.x, p3.y, ah[mt][3], al[mt][3]);
            }
            uint32_t bh[4][4], bl[4][4];
            #pragma unroll
            for (int i = 0; i < 4; i++) {
                uint32_t a = aB1 + (uint32_t)i * 16 * 272 + kk * 32;
                ldsm4(bh[i], a);
                ldsm4(bl[i], a + 17408);
            }
            #pragma unroll
            for (int mt = 0; mt < 2; mt++)
                #pragma unroll
                for (int nt = 0; nt < 8; nt++) {
                    const uint32_t* bhp = &bh[nt >> 1][(nt & 1) * 2];
                    const uint32_t* blp = &bl[nt >> 1][(nt & 1) * 2];
                    mma_bf16(acc1[mt][nt], ah[mt], bhp);
                    mma_bf16(acc1[mt][nt], al[mt], bhp);
                    mma_bf16(acc1[mt][nt], ah[mt], blp);
                }
        }
        // ---- convert: bias+relu, C-frags -> A-frags of GEMM2 (registers only) ----
        uint32_t fh[2][4][4], fl[2][4][4];
        #pragma unroll
        for (int mt = 0; mt < 2; mt++)
            #pragma unroll
            for (int j = 0; j < 4; j++) {
                float2 ba = *reinterpret_cast<const float2*>(b1v + 16 * j + 2 * ec);
                float2 bb = *reinterpret_cast<const float2*>(b1v + 16 * j + 8 + 2 * ec);
                float v00 = fmaxf(acc1[mt][2 * j][0] + ba.x, 0.f);
                float v01 = fmaxf(acc1[mt][2 * j][1] + ba.y, 0.f);
                float v10 = fmaxf(acc1[mt][2 * j][2] + ba.x, 0.f);
                float v11 = fmaxf(acc1[mt][2 * j][3] + ba.y, 0.f);
                float w00 = fmaxf(acc1[mt][2 * j + 1][0] + bb.x, 0.f);
                float w01 = fmaxf(acc1[mt][2 * j + 1][1] + bb.y, 0.f);
                float w10 = fmaxf(acc1[mt][2 * j + 1][2] + bb.x, 0.f);
                float w11 = fmaxf(acc1[mt][2 * j + 1][3] + bb.y, 0.f);
                split2(v00, v01, fh[mt][j][0], fl[mt][j][0]);
                split2(v10, v11, fh[mt][j][1], fl[mt][j][1]);
                split2(w00, w01, fh[mt][j][2], fl[mt][j][2]);
                split2(w10, w11, fh[mt][j][3], fl[mt][j][3]);
            }
        // ---- GEMM2: acc2[2 mt][8 nt] = Mid[m32 x k64] @ B2^T ----
        float acc2[2][8][4];
        #pragma unroll
        for (int mt = 0; mt < 2; mt++)
            #pragma unroll
            for (int nt = 0; nt < 8; nt++)
                #pragma unroll
                for (int j = 0; j < 4; j++) acc2[mt][nt][j] = 0.f;
        #pragma unroll
        for (int kk = 0; kk < 4; kk++) {
            uint32_t bh[4][4], bl[4][4];
            #pragma unroll
            for (int i = 0; i < 4; i++) {
                uint32_t a = aB2 + (uint32_t)i * 16 * 144 + kk * 32;
                ldsm4(bh[i], a);
                ldsm4(bl[i], a + 9216);
            }
            #pragma unroll
            for (int mt = 0; mt < 2; mt++)
                #pragma unroll
                for (int nt = 0; nt < 8; nt++) {
                    const uint32_t* bhp = &bh[nt >> 1][(nt & 1) * 2];
                    const uint32_t* blp = &bl[nt >> 1][(nt & 1) * 2];
                    mma_bf16(acc2[mt][nt], fh[mt][kk], bhp);
                    mma_bf16(acc2[mt][nt], fl[mt][kk], bhp);
                    mma_bf16(acc2[mt][nt], fh[mt][kk], blp);
                }
        }
        // ---- epilogue: bias+relu -> scatter/store ----
        #pragma unroll
        for (int mt = 0; mt < 2; mt++)
            #pragma unroll
            for (int nt = 0; nt < 8; nt++) {
                int n = 8 * nt + 2 * ec;
                float2 bb = *reinterpret_cast<const float2*>(b2v + n);
                float v00 = fmaxf(acc2[mt][nt][0] + bb.x, 0.f);
                float v01 = fmaxf(acc2[mt][nt][1] + bb.y, 0.f);
                float v10 = fmaxf(acc2[mt][nt][2] + bb.x, 0.f);
                float v11 = fmaxf(acc2[mt][nt][3] + bb.y, 0.f);
                if (EDGE) {
                    float* p0 = g_agg + (size_t)dd[2 * mt] * HID + n;
                    float* p1 = g_agg + (size_t)dd[2 * mt + 1] * HID + n;
                    asm volatile("red.global.add.v2.f32 [%0], {%1,%2};"
                                 :: "l"(p0), "f"(v00), "f"(v01) : "memory");
                    asm volatile("red.global.add.v2.f32 [%0], {%1,%2};"
                                 :: "l"(p1), "f"(v10), "f"(v11) : "memory");
                } else {
                    *reinterpret_cast<float2*>(g_u + (size_t)dd[2 * mt] * HID + n) =
                        make_float2(v00, v01);
                    *reinterpret_cast<float2*>(g_u + (size_t)dd[2 * mt + 1] * HID + n) =
                        make_float2(v10, v11);
                }
            }
    }
}

// ---------------- InstanceNorm: 64 blocks = (graph, 16-ch quad) ----------------
__global__ void instnorm_kernel() {
    int g = blockIdx.x >> 2, cq = (blockIdx.x & 3) << 4;
    int t = threadIdx.x;          // 512
    int c = t & 15, r = t >> 4;   // r 0..31
    const float* basep = g_u + (size_t)g * NS * HID + cq + c;
    float* outp = g_h + (size_t)g * NS * HID + cq + c;
    __shared__ float red[32][16];
    float s = 0.f;
    for (int n = r; n < NS; n += 32) s += basep[(size_t)n * HID];
    red[r][c] = s;
    __syncthreads();
    if (r == 0) {
        float tot = 0.f;
        #pragma unroll
        for (int i = 0; i < 32; i++) tot += red[i][c];
        red[0][c] = tot * (1.0f / NS);
    }
    __syncthreads();
    float mean = red[0][c];
    __syncthreads();
    float s2 = 0.f;
    for (int n = r; n < NS; n += 32) {
        float d = basep[(size_t)n * HID] - mean;
        s2 = fmaf(d, d, s2);
    }
    red[r][c] = s2;
    __syncthreads();
    if (r == 0) {
        float tot = 0.f;
        #pragma unroll
        for (int i = 0; i < 32; i++) tot += red[i][c];
        red[0][c] = rsqrtf(tot * (1.0f / NS) + EPSF);
    }
    __syncthreads();
    float inv = red[0][c];
    for (int n = r; n < NS; n += 32)
        outp[(size_t)n * HID] = (basep[(size_t)n * HID] - mean) * inv;
}

// ---------------- decoder ----------------
__global__ void decoder_kernel(const float* __restrict__ W, const float* __restrict__ b,
                               float* __restrict__ out) {
    __shared__ float sW[HID * 3];
    __shared__ float sb[3];
    int t = threadIdx.x;
    if (t < HID * 3) sW[t] = W[t];
    if (t < 3) sb[t] = b[t];
    __syncthreads();
    int n = blockIdx.x * 256 + t;
    float a0 = sb[0], a1 = sb[1], a2 = sb[2];
    const float* hr = g_h + (size_t)n * HID;
    #pragma unroll 8
    for (int k = 0; k < HID; k++) {
        float v = hr[k];
        a0 = fmaf(v, sW[k * 3 + 0], a0);
        a1 = fmaf(v, sW[k * 3 + 1], a1);
        a2 = fmaf(v, sW[k * 3 + 2], a2);
    }
    float inv = rsqrtf(a0 * a0 + a1 * a1 + a2 * a2);
    a0 *= inv; a1 *= inv; a2 *= inv;
    g_X[n * 3 + 0] = a0; g_X[n * 3 + 1] = a1; g_X[n * 3 + 2] = a2;
    out[1 + n * 3 + 0] = a0; out[1 + n * 3 + 1] = a1; out[1 + n * 3 + 2] = a2;
}

// ---------------- MMD kernels ----------------
__global__ void kxx_kernel() {
    int bid = blockIdx.x;
    int g = bid >> 8, tm = (bid >> 4) & 15, tn = bid & 15;
    const float* Xg = g_X + (size_t)g * NS * 3;
    __shared__ float ax[128][4];
    __shared__ float ay[128][4];
    __shared__ float rs[256];
    int t = threadIdx.x;
    for (int i = t; i < 128 * 3; i += 256) {
        int row = i / 3, col = i - row * 3;
        ax[row][col] = Xg[tm * 128 * 3 + i];
        ay[row][col] = Xg[tn * 128 * 3 + i];
    }
    __syncthreads();
    int r0 = (t >> 4) << 3, cb = (t & 15) << 3;
    float yv[8][3];
    #pragma unroll
    for (int j = 0; j < 8; j++) {
        yv[j][0] = ay[cb + j][0]; yv[j][1] = ay[cb + j][1]; yv[j][2] = ay[cb + j][2];
    }
    float s = 0.f;
    #pragma unroll
    for (int i = 0; i < 8; i++) {
        float x0 = ax[r0 + i][0], x1 = ax[r0 + i][1], x2 = ax[r0 + i][2];
        #pragma unroll
        for (int j = 0; j < 8; j++) {
            float d = fmaf(x0, yv[j][0], fmaf(x1, yv[j][1], x2 * yv[j][2]));
            s += fexp(fmaf(2.f, d, -2.f));
        }
    }
    rs[t] = s;
    __syncthreads();
    for (int o = 128; o > 0; o >>= 1) { if (t < o) rs[t] += rs[t + o]; __syncthreads(); }
    if (t == 0) atomicAdd(&g_acc[g], rs[0]);
}

__global__ void kxy_kernel() {
    __shared__ float sy[64][4];
    __shared__ float rs[256];
    int t = threadIdx.x;
    int n = blockIdx.x * 256 + t;
    for (int i = t; i < 64 * 3; i += 256) { int row = i / 3; sy[row][i - row * 3] = g_Y[i]; }
    __syncthreads();
    float x0 = g_X[n * 3], x1 = g_X[n * 3 + 1], x2 = g_X[n * 3 + 2];
    float s = 0.f;
    #pragma unroll 8
    for (int j = 0; j < 64; j++) {
        float d = fmaf(x0, sy[j][0], fmaf(x1, sy[j][1], x2 * sy[j][2]));
        s += fexp(fmaf(2.f, d, -2.f));
    }
    rs[t] = s;
    __syncthreads();
    for (int o = 128; o > 0; o >>= 1) { if (t < o) rs[t] += rs[t + o]; __syncthreads(); }
    if (t == 0) atomicAdd(&g_acc[NBATCH + (n >> 11)], rs[0]);
}

__global__ void finalize_kernel(float* __restrict__ out) {
    __shared__ float rs[64];
    int t = threadIdx.x;
    float x0 = g_Y[t * 3], x1 = g_Y[t * 3 + 1], x2 = g_Y[t * 3 + 2];
    float s = 0.f;
    for (int j = 0; j < 64; j++) {
        float d = fmaf(x0, g_Y[j * 3], fmaf(x1, g_Y[j * 3 + 1], x2 * g_Y[j * 3 + 2]));
        s += fexp(fmaf(2.f, d, -2.f));
    }
    rs[t] = s;
    __syncthreads();
    if (t == 0) {
        float kyy = 0.f;
        for (int j = 0; j < 64; j++) kyy += rs[j];
        kyy *= (1.0f / (64.f * 64.f));
        float loss = 0.f;
        for (int b = 0; b < NBATCH; b++) {
            float kxx = g_acc[b] * (1.0f / ((float)NS * (float)NS));
            float kxy = g_acc[NBATCH + b] * (1.0f / ((float)NS * 64.f));
            loss += kxx - 2.f * kxy + kyy;
        }
        out[0] = loss * (1.0f / NBATCH);
    }
}

// ---------------- launch ----------------
extern "C" void kernel_launch(void* const* d_in, const int* in_sizes, int n_in,
                              void* d_out, int out_size) {
    const float* x    = (const float*)d_in[0];
    const int*   esrc = (const int*)d_in[1];
    const int*   edst = (const int*)d_in[2];
    const float* encW = (const float*)d_in[4];
    const float* encb = (const float*)d_in[5];
    const float* m1W  = (const float*)d_in[6];
    const float* m1b  = (const float*)d_in[7];
    const float* m2W  = (const float*)d_in[8];
    const float* m2b  = (const float*)d_in[9];
    const float* u1W  = (const float*)d_in[10];
    const float* u1b  = (const float*)d_in[11];
    const float* u2W  = (const float*)d_in[12];
    const float* u2b  = (const float*)d_in[13];
    const float* decW = (const float*)d_in[14];
    const float* decb = (const float*)d_in[15];
    float* out = (float*)d_out;

    cudaFuncSetAttribute((const void*)mlp_mma_kernel<true>,
                         cudaFuncAttributeMaxDynamicSharedMemorySize, SMEM_MMA_BYTES);
    cudaFuncSetAttribute((const void*)mlp_mma_kernel<false>,
                         cudaFuncAttributeMaxDynamicSharedMemorySize, SMEM_MMA_BYTES);

    compute_Y_kernel<<<1, 64>>>();
    encoder_kernel<<<NNODES * HID / 256, 256>>>(x, encW, encb);

    for (int l = 0; l < 4; l++) {
        zero_agg_kernel<<<NNODES * HID / 1024, 256>>>();
        mlp_mma_kernel<true><<<444, 128, SMEM_MMA_BYTES>>>(
            m1W + (size_t)l * 128 * 64, m1b + (size_t)l * 64,
            m2W + (size_t)l * 64 * 64,  m2b + (size_t)l * 64, esrc, edst);
        mlp_mma_kernel<false><<<256, 128, SMEM_MMA_BYTES>>>(
            u1W + (size_t)l * 128 * 64, u1b + (size_t)l * 64,
            u2W + (size_t)l * 64 * 64,  u2b + (size_t)l * 64, nullptr, nullptr);
        instnorm_kernel<<<64, 512>>>();
    }

    zero_acc_kernel<<<1, 32>>>();
    decoder_kernel<<<NNODES / 256, 256>>>(decW, decb, out);
    kxy_kernel<<<NNODES / 256, 256>>>();
    kxx_kernel<<<NBATCH * 16 * 16, 256>>>();
    finalize_kernel<<<1, 64>>>(out);
}

// round 14
// speedup vs baseline: 1.0539x; 1.0208x over previous
#include <cuda_runtime.h>
#include <cuda_bf16.h>
#include <math.h>
#include <stdint.h>

#define NNODES 32768
#define NBATCH 16
#define NS 2048
#define HID 64
#define ETOT 524288
#define EPSF 1e-5f

// ---------------- scratch ----------------
__device__ float g_h[NNODES * HID];
__device__ float g_agg[NNODES * HID];
__device__ float g_u[NNODES * HID];
__device__ float g_PQ[NNODES * 128];   // per-node P = h@W1top + b1 (cols 0-63), Q = h@W1bot (cols 64-127)
__device__ float g_X[NNODES * 3];
__device__ float g_Y[64 * 3];
__device__ float g_acc[2 * NBATCH];

// ---------------- node-MLP smem (weights only) ----------------
#define B1_HI  0
#define B1_LO  17408
#define B2_HI  34816
#define B2_LO  44032
#define BIAS1  53248
#define BIAS2  53504
#define SMEM_MMA_BYTES 53760

// ---------------- edge smem: B2 only ----------------
#define E_B2_HI  0
#define E_B2_LO  9216
#define E_BIAS2  18432
#define SMEM_EDGE_BYTES 18688

// ---------------- precompute smem: B1^T [128n][72k] ----------------
#define P_B1_HI  0
#define P_B1_LO  18432
#define P_BIAS1  36864
#define SMEM_PRE_BYTES 37120

static __device__ __forceinline__ uint32_t cvta_smem(const void* p) {
    uint32_t a;
    asm("{ .reg .u64 t; cvta.to.shared.u64 t, %1; cvt.u32.u64 %0, t; }" : "=r"(a) : "l"(p));
    return a;
}
static __device__ __forceinline__ void ldsm4(uint32_t* r, uint32_t addr) {
    asm volatile("ldmatrix.sync.aligned.m8n8.x4.shared.b16 {%0,%1,%2,%3}, [%4];"
                 : "=r"(r[0]), "=r"(r[1]), "=r"(r[2]), "=r"(r[3]) : "r"(addr));
}
static __device__ __forceinline__ void mma_bf16(float* c, const uint32_t* a, const uint32_t* b) {
    asm volatile(
        "mma.sync.aligned.m16n8k16.row.col.f32.bf16.bf16.f32 "
        "{%0,%1,%2,%3}, {%4,%5,%6,%7}, {%8,%9}, {%0,%1,%2,%3};"
        : "+f"(c[0]), "+f"(c[1]), "+f"(c[2]), "+f"(c[3])
        : "r"(a[0]), "r"(a[1]), "r"(a[2]), "r"(a[3]), "r"(b[0]), "r"(b[1]));
}
static __device__ __forceinline__ void split2(float x, float y, uint32_t& hi, uint32_t& lo) {
    __nv_bfloat16 hx = __float2bfloat16(x), hy = __float2bfloat16(y);
    __nv_bfloat16 lx = __float2bfloat16(x - __bfloat162float(hx));
    __nv_bfloat16 ly = __float2bfloat16(y - __bfloat162float(hy));
    hi = ((uint32_t)__bfloat16_as_ushort(hy) << 16) | (uint32_t)__bfloat16_as_ushort(hx);
    lo = ((uint32_t)__bfloat16_as_ushort(ly) << 16) | (uint32_t)__bfloat16_as_ushort(lx);
}

// fast exp, FFMA-only
__device__ __forceinline__ float fexp(float x) {
    const float L2E = 1.4426950408889634f;
    float t = fmaf(x, L2E, 12582912.0f);
    float kf = t - 12582912.0f;
    float f = fmaf(x, L2E, -kf);
    float p = 1.33335581e-3f;
    p = fmaf(p, f, 9.61812911e-3f);
    p = fmaf(p, f, 5.55041087e-2f);
    p = fmaf(p, f, 2.40226507e-1f);
    p = fmaf(p, f, 6.93147181e-1f);
    p = fmaf(p, f, 1.0f);
    int ik = (int)kf;
    return __int_as_float(__float_as_int(p) + (ik << 23));
}

__global__ void compute_Y_kernel() {
    int i = threadIdx.x;
    if (i < 64) {
        double phi = 3.14159265358979323846 * (3.0 - sqrt(5.0));
        double y = 1.0 - 2.0 * (double)i / 63.0;
        double r = sqrt(fmax(0.0, 1.0 - y * y));
        double th = phi * (double)i;
        g_Y[i * 3 + 0] = (float)(cos(th) * r);
        g_Y[i * 3 + 1] = (float)y;
        g_Y[i * 3 + 2] = (float)(sin(th) * r);
    }
}

__global__ void zero_agg_kernel() {
    int i = blockIdx.x * blockDim.x + threadIdx.x;
    reinterpret_cast<float4*>(g_agg)[i] = make_float4(0.f, 0.f, 0.f, 0.f);
}

__global__ void zero_acc_kernel() {
    int i = threadIdx.x;
    if (i < 2 * NBATCH) g_acc[i] = 0.f;
}

__global__ void encoder_kernel(const float* __restrict__ x,
                               const float* __restrict__ W,
                               const float* __restrict__ b) {
    __shared__ float sW[3 * HID];
    __shared__ float sb[HID];
    int t = threadIdx.x;
    if (t < 3 * HID) sW[t] = W[t];
    if (t < HID) sb[t] = b[t];
    __syncthreads();
    int idx = blockIdx.x * 256 + t;
    int n = idx >> 6, c = idx & 63;
    float x0 = x[n * 3 + 0], x1 = x[n * 3 + 1], x2 = x[n * 3 + 2];
    g_h[idx] = fmaf(x0, sW[c], fmaf(x1, sW[HID + c], fmaf(x2, sW[2 * HID + c], sb[c])));
}

// ============ precompute: PQ = h @ [W1top | W1bot] (+b1 on P half) ============
// 256 threads (8 warps), warp = m16 x n64 per half, 128 rows/tile, 256 tiles.
__global__ void __launch_bounds__(256, 2) precompute_kernel(
    const float* __restrict__ W1g, const float* __restrict__ b1g) {
    extern __shared__ char sp[];
    const uint32_t sb = cvta_smem(sp);
    const int t = threadIdx.x, lane = t & 31, wid = t >> 5;
    float* b1v = reinterpret_cast<float*>(sp + P_BIAS1);

    // B1^T [128 n][72 k pad]: rows 0-63 = W1top^T (P), rows 64-127 = W1bot^T (Q)
    for (int i = t; i < 128 * 64; i += 256) {
        int k = i >> 6, n = i & 63;
        float w = W1g[i];
        __nv_bfloat16 hi = __float2bfloat16(w);
        __nv_bfloat16 lo = __float2bfloat16(w - __bfloat162float(hi));
        int nn = (k < 64) ? n : (64 + n);
        int k2 = k & 63;
        reinterpret_cast<__nv_bfloat16*>(sp + P_B1_HI)[nn * 72 + k2] = hi;
        reinterpret_cast<__nv_bfloat16*>(sp + P_B1_LO)[nn * 72 + k2] = lo;
    }
    if (t < 64) b1v[t] = b1g[t];
    __syncthreads();

    const int g = lane >> 3;
    const int b_row = (g >> 1) * 8 + (lane & 7);
    const int b_koff = (g & 1) * 8;
    const int er = lane >> 2, ec = lane & 3;
    const int m0 = wid * 16;
    const uint32_t aB = sb + P_B1_HI + (uint32_t)b_row * 144 + b_koff * 2;

    for (int tile = blockIdx.x; tile < NNODES / 128; tile += gridDim.x) {
        const int r0 = tile * 128 + m0 + er, r1 = r0 + 8;
        const float* ha = g_h + (size_t)r0 * HID;
        const float* hb = g_h + (size_t)r1 * HID;
        // A fragments (once)
        uint32_t ah[4][4], al[4][4];
        #pragma unroll
        for (int kk = 0; kk < 4; kk++) {
            int cb = kk * 16 + 2 * ec;
            float2 p0 = *reinterpret_cast<const float2*>(ha + cb);
            float2 p1 = *reinterpret_cast<const float2*>(hb + cb);
            float2 p2 = *reinterpret_cast<const float2*>(ha + cb + 8);
            float2 p3 = *reinterpret_cast<const float2*>(hb + cb + 8);
            split2(p0.x, p0.y, ah[kk][0], al[kk][0]);
            split2(p1.x, p1.y, ah[kk][1], al[kk][1]);
            split2(p2.x, p2.y, ah[kk][2], al[kk][2]);
            split2(p3.x, p3.y, ah[kk][3], al[kk][3]);
        }
        #pragma unroll
        for (int half = 0; half < 2; half++) {
            float acc[8][4];
            #pragma unroll
            for (int nt = 0; nt < 8; nt++)
                #pragma unroll
                for (int j = 0; j < 4; j++) acc[nt][j] = 0.f;
            #pragma unroll
            for (int kk = 0; kk < 4; kk++) {
                uint32_t bh[4][4], bl[4][4];
                #pragma unroll
                for (int i = 0; i < 4; i++) {
                    uint32_t a = aB + (uint32_t)(half * 64 + i * 16) * 144 + kk * 32;
                    ldsm4(bh[i], a);
                    ldsm4(bl[i], a + 18432);
                }
                #pragma unroll
                for (int nt = 0; nt < 8; nt++) {
                    const uint32_t* bhp = &bh[nt >> 1][(nt & 1) * 2];
                    const uint32_t* blp = &bl[nt >> 1][(nt & 1) * 2];
                    mma_bf16(acc[nt], ah[kk], bhp);
                    mma_bf16(acc[nt], al[kk], bhp);
                    mma_bf16(acc[nt], ah[kk], blp);
                }
            }
            float* o0 = g_PQ + (size_t)r0 * 128 + half * 64;
            float* o1 = g_PQ + (size_t)r1 * 128 + half * 64;
            #pragma unroll
            for (int nt = 0; nt < 8; nt++) {
                int n = 8 * nt + 2 * ec;
                float bx = half ? 0.f : b1v[n];
                float by = half ? 0.f : b1v[n + 1];
                *reinterpret_cast<float2*>(o0 + n) = make_float2(acc[nt][0] + bx, acc[nt][1] + by);
                *reinterpret_cast<float2*>(o1 + n) = make_float2(acc[nt][2] + bx, acc[nt][3] + by);
            }
        }
    }
}

// ============ edge: Mid = relu(P[dst]+Q[src]); agg[dst] += relu(Mid@W2+b2) ============
// 128 threads (4 warps), warp = m32 processed as two sequential m16 halves. 4 CTAs/SM.
__global__ void __launch_bounds__(128, 4) edge_pq_kernel(
    const float* __restrict__ W2g, const float* __restrict__ b2g,
    const int* __restrict__ esrc, const int* __restrict__ edst) {
    extern __shared__ char sp[];
    const uint32_t sb = cvta_smem(sp);
    const int t = threadIdx.x, lane = t & 31, wid = t >> 5;
    float* b2v = reinterpret_cast<float*>(sp + E_BIAS2);

    for (int i = t; i < 64 * 64; i += 128) {
        int k = i >> 6, n = i & 63;
        float w = W2g[i];
        __nv_bfloat16 hi = __float2bfloat16(w);
        __nv_bfloat16 lo = __float2bfloat16(w - __bfloat162float(hi));
        reinterpret_cast<__nv_bfloat16*>(sp + E_B2_HI)[n * 72 + k] = hi;
        reinterpret_cast<__nv_bfloat16*>(sp + E_B2_LO)[n * 72 + k] = lo;
    }
    if (t < 64) b2v[t] = b2g[t];
    __syncthreads();

    const int g = lane >> 3;
    const int b_row = (g >> 1) * 8 + (lane & 7);
    const int b_koff = (g & 1) * 8;
    const int er = lane >> 2, ec = lane & 3;
    const int m0 = wid * 32;
    const uint32_t aB2 = sb + E_B2_HI + (uint32_t)b_row * 144 + b_koff * 2;

    for (int tile = blockIdx.x; tile < ETOT / 128; tile += gridDim.x) {
        const int base = tile * 128;
        int dd[4], ss[4];
        #pragma unroll
        for (int i = 0; i < 4; i++) {
            int r = base + m0 + 8 * i + er;
            dd[i] = edst[r];
            ss[i] = esrc[r];
        }
        #pragma unroll
        for (int mt = 0; mt < 2; mt++) {
            const float* P0 = g_PQ + (size_t)dd[2 * mt] * 128;
            const float* P1 = g_PQ + (size_t)dd[2 * mt + 1] * 128;
            const float* Q0 = g_PQ + (size_t)ss[2 * mt] * 128 + 64;
            const float* Q1 = g_PQ + (size_t)ss[2 * mt + 1] * 128 + 64;
            uint32_t fh[4][4], fl[4][4];
            #pragma unroll
            for (int kk = 0; kk < 4; kk++) {
                int cb = kk * 16 + 2 * ec;
                float2 pa = *reinterpret_cast<const float2*>(P0 + cb);
                float2 qa = *reinterpret_cast<const float2*>(Q0 + cb);
                float2 pb = *reinterpret_cast<const float2*>(P1 + cb);
                float2 qb = *reinterpret_cast<const float2*>(Q1 + cb);
                float2 pc = *reinterpret_cast<const float2*>(P0 + cb + 8);
                float2 qc = *reinterpret_cast<const float2*>(Q0 + cb + 8);
                float2 pd = *reinterpret_cast<const float2*>(P1 + cb + 8);
                float2 qd = *reinterpret_cast<const float2*>(Q1 + cb + 8);
                split2(fmaxf(pa.x + qa.x, 0.f), fmaxf(pa.y + qa.y, 0.f), fh[kk][0], fl[kk][0]);
                split2(fmaxf(pb.x + qb.x, 0.f), fmaxf(pb.y + qb.y, 0.f), fh[kk][1], fl[kk][1]);
                split2(fmaxf(pc.x + qc.x, 0.f), fmaxf(pc.y + qc.y, 0.f), fh[kk][2], fl[kk][2]);
                split2(fmaxf(pd.x + qd.x, 0.f), fmaxf(pd.y + qd.y, 0.f), fh[kk][3], fl[kk][3]);
            }
            float acc2[8][4];
            #pragma unroll
            for (int nt = 0; nt < 8; nt++)
                #pragma unroll
                for (int j = 0; j < 4; j++) acc2[nt][j] = 0.f;
            #pragma unroll
            for (int kk = 0; kk < 4; kk++) {
                uint32_t bh[4][4], bl[4][4];
                #pragma unroll
                for (int i = 0; i < 4; i++) {
                    uint32_t a = aB2 + (uint32_t)i * 16 * 144 + kk * 32;
                    ldsm4(bh[i], a);
                    ldsm4(bl[i], a + 9216);
                }
                #pragma unroll
                for (int nt = 0; nt < 8; nt++) {
                    const uint32_t* bhp = &bh[nt >> 1][(nt & 1) * 2];
                    const uint32_t* blp = &bl[nt >> 1][(nt & 1) * 2];
                    mma_bf16(acc2[nt], fh[kk], bhp);
                    mma_bf16(acc2[nt], fl[kk], bhp);
                    mma_bf16(acc2[nt], fh[kk], blp);
                }
            }
            #pragma unroll
            for (int nt = 0; nt < 8; nt++) {
                int n = 8 * nt + 2 * ec;
                float2 bb = *reinterpret_cast<const float2*>(b2v + n);
                float v00 = fmaxf(acc2[nt][0] + bb.x, 0.f);
                float v01 = fmaxf(acc2[nt][1] + bb.y, 0.f);
                float v10 = fmaxf(acc2[nt][2] + bb.x, 0.f);
                float v11 = fmaxf(acc2[nt][3] + bb.y, 0.f);
                float* p0 = g_agg + (size_t)dd[2 * mt] * HID + n;
                float* p1 = g_agg + (size_t)dd[2 * mt + 1] * HID + n;
                asm volatile("red.global.add.v2.f32 [%0], {%1,%2};"
                             :: "l"(p0), "f"(v00), "f"(v01) : "memory");
                asm volatile("red.global.add.v2.f32 [%0], {%1,%2};"
                             :: "l"(p1), "f"(v10), "f"(v11) : "memory");
            }
        }
    }
}

// ============ node MLP (unchanged R12 structure, EDGE=false) ============
__global__ void __launch_bounds__(128, 3) node_mma_kernel(
    const float* __restrict__ W1g, const float* __restrict__ b1g,
    const float* __restrict__ W2g, const float* __restrict__ b2g) {
    extern __shared__ char sp[];
    const uint32_t sb = cvta_smem(sp);
    const int t = threadIdx.x, lane = t & 31, wid = t >> 5;

    float* b1v = reinterpret_cast<float*>(sp + BIAS1);
    float* b2v = reinterpret_cast<float*>(sp + BIAS2);

    for (int i = t; i < 128 * 64; i += 128) {
        int k = i >> 6, n = i & 63;
        float w = W1g[i];
        __nv_bfloat16 hi = __float2bfloat16(w);
        __nv_bfloat16 lo = __float2bfloat16(w - __bfloat162float(hi));
        reinterpret_cast<__nv_bfloat16*>(sp + B1_HI)[n * 136 + k] = hi;
        reinterpret_cast<__nv_bfloat16*>(sp + B1_LO)[n * 136 + k] = lo;
    }
    for (int i = t; i < 64 * 64; i += 128) {
        int k = i >> 6, n = i & 63;
        float w = W2g[i];
        __nv_bfloat16 hi = __float2bfloat16(w);
        __nv_bfloat16 lo = __float2bfloat16(w - __bfloat162float(hi));
        reinterpret_cast<__nv_bfloat16*>(sp + B2_HI)[n * 72 + k] = hi;
        reinterpret_cast<__nv_bfloat16*>(sp + B2_LO)[n * 72 + k] = lo;
    }
    if (t < 64) { b1v[t] = b1g[t]; b2v[t] = b2g[t]; }
    __syncthreads();

    const int g = lane >> 3;
    const int b_row = (g >> 1) * 8 + (lane & 7);
    const int b_koff = (g & 1) * 8;
    const int er = lane >> 2, ec = lane & 3;
    const int m0 = wid * 32;

    const uint32_t aB1 = sb + B1_HI + (uint32_t)b_row * 272 + b_koff * 2;
    const uint32_t aB2 = sb + B2_HI + (uint32_t)b_row * 144 + b_koff * 2;

    for (int tile = blockIdx.x; tile < NNODES / 128; tile += gridDim.x) {
        const int base = tile * 128;
        int rr[4];
        #pragma unroll
        for (int i = 0; i < 4; i++) rr[i] = base + m0 + 8 * i + er;

        float acc1[2][8][4];
        #pragma unroll
        for (int mt = 0; mt < 2; mt++)
            #pragma unroll
            for (int nt = 0; nt < 8; nt++)
                #pragma unroll
                for (int j = 0; j < 4; j++) acc1[mt][nt][j] = 0.f;
        #pragma unroll
        for (int kk = 0; kk < 8; kk++) {
            const int kb = (kk & 3) * 16;
            uint32_t ah[2][4], al[2][4];
            #pragma unroll
            for (int mt = 0; mt < 2; mt++) {
                const float* src = (kk < 4) ? g_h : g_agg;
                const float* qa = src + (size_t)rr[2 * mt] * HID;
                const float* qb = src + (size_t)rr[2 * mt + 1] * HID;
                float2 p0 = *reinterpret_cast<const float2*>(qa + kb + 2 * ec);
                float2 p1 = *reinterpret_cast<const float2*>(qb + kb + 2 * ec);
                float2 p2 = *reinterpret_cast<const float2*>(qa + kb + 8 + 2 * ec);
                float2 p3 = *reinterpret_cast<const float2*>(qb + kb + 8 + 2 * ec);
                split2(p0.x, p0.y, ah[mt][0], al[mt][0]);
                split2(p1.x, p1.y, ah[mt][1], al[mt][1]);
                split2(p2.x, p2.y, ah[mt][2], al[mt][2]);
                split2(p3.x, p3.y, ah[mt][3], al[mt][3]);
            }
            uint32_t bh[4][4], bl[4][4];
            #pragma unroll
            for (int i = 0; i < 4; i++) {
                uint32_t a = aB1 + (uint32_t)i * 16 * 272 + kk * 32;
                ldsm4(bh[i], a);
                ldsm4(bl[i], a + 17408);
            }
            #pragma unroll
            for (int mt = 0; mt < 2; mt++)
                #pragma unroll
                for (int nt = 0; nt < 8; nt++) {
                    const uint32_t* bhp = &bh[nt >> 1][(nt & 1) * 2];
                    const uint32_t* blp = &bl[nt >> 1][(nt & 1) * 2];
                    mma_bf16(acc1[mt][nt], ah[mt], bhp);
                    mma_bf16(acc1[mt][nt], al[mt], bhp);
                    mma_bf16(acc1[mt][nt], ah[mt], blp);
                }
        }
        uint32_t fh[2][4][4], fl[2][4][4];
        #pragma unroll
        for (int mt = 0; mt < 2; mt++)
            #pragma unroll
            for (int j = 0; j < 4; j++) {
                float2 ba = *reinterpret_cast<const float2*>(b1v + 16 * j + 2 * ec);
                float2 bb = *reinterpret_cast<const float2*>(b1v + 16 * j + 8 + 2 * ec);
                float v00 = fmaxf(acc1[mt][2 * j][0] + ba.x, 0.f);
                float v01 = fmaxf(acc1[mt][2 * j][1] + ba.y, 0.f);
                float v10 = fmaxf(acc1[mt][2 * j][2] + ba.x, 0.f);
                float v11 = fmaxf(acc1[mt][2 * j][3] + ba.y, 0.f);
                float w00 = fmaxf(acc1[mt][2 * j + 1][0] + bb.x, 0.f);
                float w01 = fmaxf(acc1[mt][2 * j + 1][1] + bb.y, 0.f);
                float w10 = fmaxf(acc1[mt][2 * j + 1][2] + bb.x, 0.f);
                float w11 = fmaxf(acc1[mt][2 * j + 1][3] + bb.y, 0.f);
                split2(v00, v01, fh[mt][j][0], fl[mt][j][0]);
                split2(v10, v11, fh[mt][j][1], fl[mt][j][1]);
                split2(w00, w01, fh[mt][j][2], fl[mt][j][2]);
                split2(w10, w11, fh[mt][j][3], fl[mt][j][3]);
            }
        float acc2[2][8][4];
        #pragma unroll
        for (int mt = 0; mt < 2; mt++)
            #pragma unroll
            for (int nt = 0; nt < 8; nt++)
                #pragma unroll
                for (int j = 0; j < 4; j++) acc2[mt][nt][j] = 0.f;
        #pragma unroll
        for (int kk = 0; kk < 4; kk++) {
            uint32_t bh[4][4], bl[4][4];
            #pragma unroll
            for (int i = 0; i < 4; i++) {
                uint32_t a = aB2 + (uint32_t)i * 16 * 144 + kk * 32;
                ldsm4(bh[i], a);
                ldsm4(bl[i], a + 9216);
            }
            #pragma unroll
            for (int mt = 0; mt < 2; mt++)
                #pragma unroll
                for (int nt = 0; nt < 8; nt++) {
                    const uint32_t* bhp = &bh[nt >> 1][(nt & 1) * 2];
                    const uint32_t* blp = &bl[nt >> 1][(nt & 1) * 2];
                    mma_bf16(acc2[mt][nt], fh[mt][kk], bhp);
                    mma_bf16(acc2[mt][nt], fl[mt][kk], bhp);
                    mma_bf16(acc2[mt][nt], fh[mt][kk], blp);
                }
        }
        #pragma unroll
        for (int mt = 0; mt < 2; mt++)
            #pragma unroll
            for (int nt = 0; nt < 8; nt++) {
                int n = 8 * nt + 2 * ec;
                float2 bb = *reinterpret_cast<const float2*>(b2v + n);
                float v00 = fmaxf(acc2[mt][nt][0] + bb.x, 0.f);
                float v01 = fmaxf(acc2[mt][nt][1] + bb.y, 0.f);
                float v10 = fmaxf(acc2[mt][nt][2] + bb.x, 0.f);
                float v11 = fmaxf(acc2[mt][nt][3] + bb.y, 0.f);
                *reinterpret_cast<float2*>(g_u + (size_t)rr[2 * mt] * HID + n) =
                    make_float2(v00, v01);
                *reinterpret_cast<float2*>(g_u + (size_t)rr[2 * mt + 1] * HID + n) =
                    make_float2(v10, v11);
            }
    }
}

// ---------------- InstanceNorm: 64 blocks = (graph, 16-ch quad) ----------------
__global__ void instnorm_kernel() {
    int g = blockIdx.x >> 2, cq = (blockIdx.x & 3) << 4;
    int t = threadIdx.x;          // 512
    int c = t & 15, r = t >> 4;   // r 0..31
    const float* basep = g_u + (size_t)g * NS * HID + cq + c;
    float* outp = g_h + (size_t)g * NS * HID + cq + c;
    __shared__ float red[32][16];
    float s = 0.f;
    for (int n = r; n < NS; n += 32) s += basep[(size_t)n * HID];
    red[r][c] = s;
    __syncthreads();
    if (r == 0) {
        float tot = 0.f;
        #pragma unroll
        for (int i = 0; i < 32; i++) tot += red[i][c];
        red[0][c] = tot * (1.0f / NS);
    }
    __syncthreads();
    float mean = red[0][c];
    __syncthreads();
    float s2 = 0.f;
    for (int n = r; n < NS; n += 32) {
        float d = basep[(size_t)n * HID] - mean;
        s2 = fmaf(d, d, s2);
    }
    red[r][c] = s2;
    __syncthreads();
    if (r == 0) {
        float tot = 0.f;
        #pragma unroll
        for (int i = 0; i < 32; i++) tot += red[i][c];
        red[0][c] = rsqrtf(tot * (1.0f / NS) + EPSF);
    }
    __syncthreads();
    float inv = red[0][c];
    for (int n = r; n < NS; n += 32)
        outp[(size_t)n * HID] = (basep[(size_t)n * HID] - mean) * inv;
}

// ---------------- decoder ----------------
__global__ void decoder_kernel(const float* __restrict__ W, const float* __restrict__ b,
                               float* __restrict__ out) {
    __shared__ float sW[HID * 3];
    __shared__ float sb[3];
    int t = threadIdx.x;
    if (t < HID * 3) sW[t] = W[t];
    if (t < 3) sb[t] = b[t];
    __syncthreads();
    int n = blockIdx.x * 256 + t;
    float a0 = sb[0], a1 = sb[1], a2 = sb[2];
    const float* hr = g_h + (size_t)n * HID;
    #pragma unroll 8
    for (int k = 0; k < HID; k++) {
        float v = hr[k];
        a0 = fmaf(v, sW[k * 3 + 0], a0);
        a1 = fmaf(v, sW[k * 3 + 1], a1);
        a2 = fmaf(v, sW[k * 3 + 2], a2);
    }
    float inv = rsqrtf(a0 * a0 + a1 * a1 + a2 * a2);
    a0 *= inv; a1 *= inv; a2 *= inv;
    g_X[n * 3 + 0] = a0; g_X[n * 3 + 1] = a1; g_X[n * 3 + 2] = a2;
    out[1 + n * 3 + 0] = a0; out[1 + n * 3 + 1] = a1; out[1 + n * 3 + 2] = a2;
}

// ---------------- MMD kernels ----------------
__global__ void kxx_kernel() {
    int bid = blockIdx.x;
    int g = bid >> 8, tm = (bid >> 4) & 15, tn = bid & 15;
    const float* Xg = g_X + (size_t)g * NS * 3;
    __shared__ float ax[128][4];
    __shared__ float ay[128][4];
    __shared__ float rs[256];
    int t = threadIdx.x;
    for (int i = t; i < 128 * 3; i += 256) {
        int row = i / 3, col = i - row * 3;
        ax[row][col] = Xg[tm * 128 * 3 + i];
        ay[row][col] = Xg[tn * 128 * 3 + i];
    }
    __syncthreads();
    int r0 = (t >> 4) << 3, cb = (t & 15) << 3;
    float yv[8][3];
    #pragma unroll
    for (int j = 0; j < 8; j++) {
        yv[j][0] = ay[cb + j][0]; yv[j][1] = ay[cb + j][1]; yv[j][2] = ay[cb + j][2];
    }
    float s = 0.f;
    #pragma unroll
    for (int i = 0; i < 8; i++) {
        float x0 = ax[r0 + i][0], x1 = ax[r0 + i][1], x2 = ax[r0 + i][2];
        #pragma unroll
        for (int j = 0; j < 8; j++) {
            float d = fmaf(x0, yv[j][0], fmaf(x1, yv[j][1], x2 * yv[j][2]));
            s += fexp(fmaf(2.f, d, -2.f));
        }
    }
    rs[t] = s;
    __syncthreads();
    for (int o = 128; o > 0; o >>= 1) { if (t < o) rs[t] += rs[t + o]; __syncthreads(); }
    if (t == 0) atomicAdd(&g_acc[g], rs[0]);
}

__global__ void kxy_kernel() {
    __shared__ float sy[64][4];
    __shared__ float rs[256];
    int t = threadIdx.x;
    int n = blockIdx.x * 256 + t;
    for (int i = t; i < 64 * 3; i += 256) { int row = i / 3; sy[row][i - row * 3] = g_Y[i]; }
    __syncthreads();
    float x0 = g_X[n * 3], x1 = g_X[n * 3 + 1], x2 = g_X[n * 3 + 2];
    float s = 0.f;
    #pragma unroll 8
    for (int j = 0; j < 64; j++) {
        float d = fmaf(x0, sy[j][0], fmaf(x1, sy[j][1], x2 * sy[j][2]));
        s += fexp(fmaf(2.f, d, -2.f));
    }
    rs[t] = s;
    __syncthreads();
    for (int o = 128; o > 0; o >>= 1) { if (t < o) rs[t] += rs[t + o]; __syncthreads(); }
    if (t == 0) atomicAdd(&g_acc[NBATCH + (n >> 11)], rs[0]);
}

__global__ void finalize_kernel(float* __restrict__ out) {
    __shared__ float rs[64];
    int t = threadIdx.x;
    float x0 = g_Y[t * 3], x1 = g_Y[t * 3 + 1], x2 = g_Y[t * 3 + 2];
    float s = 0.f;
    for (int j = 0; j < 64; j++) {
        float d = fmaf(x0, g_Y[j * 3], fmaf(x1, g_Y[j * 3 + 1], x2 * g_Y[j * 3 + 2]));
        s += fexp(fmaf(2.f, d, -2.f));
    }
    rs[t] = s;
    __syncthreads();
    if (t == 0) {
        float kyy = 0.f;
        for (int j = 0; j < 64; j++) kyy += rs[j];
        kyy *= (1.0f / (64.f * 64.f));
        float loss = 0.f;
        for (int b = 0; b < NBATCH; b++) {
            float kxx = g_acc[b] * (1.0f / ((float)NS * (float)NS));
            float kxy = g_acc[NBATCH + b] * (1.0f / ((float)NS * 64.f));
            loss += kxx - 2.f * kxy + kyy;
        }
        out[0] = loss * (1.0f / NBATCH);
    }
}

// ---------------- launch ----------------
extern "C" void kernel_launch(void* const* d_in, const int* in_sizes, int n_in,
                              void* d_out, int out_size) {
    const float* x    = (const float*)d_in[0];
    const int*   esrc = (const int*)d_in[1];
    const int*   edst = (const int*)d_in[2];
    const float* encW = (const float*)d_in[4];
    const float* encb = (const float*)d_in[5];
    const float* m1W  = (const float*)d_in[6];
    const float* m1b  = (const float*)d_in[7];
    const float* m2W  = (const float*)d_in[8];
    const float* m2b  = (const float*)d_in[9];
    const float* u1W  = (const float*)d_in[10];
    const float* u1b  = (const float*)d_in[11];
    const float* u2W  = (const float*)d_in[12];
    const float* u2b  = (const float*)d_in[13];
    const float* decW = (const float*)d_in[14];
    const float* decb = (const float*)d_in[15];
    float* out = (float*)d_out;

    cudaFuncSetAttribute((const void*)node_mma_kernel,
                         cudaFuncAttributeMaxDynamicSharedMemorySize, SMEM_MMA_BYTES);
    cudaFuncSetAttribute((const void*)precompute_kernel,
                         cudaFuncAttributeMaxDynamicSharedMemorySize, SMEM_PRE_BYTES);
    cudaFuncSetAttribute((const void*)edge_pq_kernel,
                         cudaFuncAttributeMaxDynamicSharedMemorySize, SMEM_EDGE_BYTES);

    compute_Y_kernel<<<1, 64>>>();
    encoder_kernel<<<NNODES * HID / 256, 256>>>(x, encW, encb);

    for (int l = 0; l < 4; l++) {
        zero_agg_kernel<<<NNODES * HID / 1024, 256>>>();
        precompute_kernel<<<148, 256, SMEM_PRE_BYTES>>>(
            m1W + (size_t)l * 128 * 64, m1b + (size_t)l * 64);
        edge_pq_kernel<<<592, 128, SMEM_EDGE_BYTES>>>(
            m2W + (size_t)l * 64 * 64, m2b + (size_t)l * 64, esrc, edst);
        node_mma_kernel<<<256, 128, SMEM_MMA_BYTES>>>(
            u1W + (size_t)l * 128 * 64, u1b + (size_t)l * 64,
            u2W + (size_t)l * 64 * 64,  u2b + (size_t)l * 64);
        instnorm_kernel<<<64, 512>>>();
    }

    zero_acc_kernel<<<1, 32>>>();
    decoder_kernel<<<NNODES / 256, 256>>>(decW, decb, out);
    kxy_kernel<<<NNODES / 256, 256>>>();
    kxx_kernel<<<NBATCH * 16 * 16, 256>>>();
    finalize_kernel<<<1, 64>>>(out);
}

// round 17
// speedup vs baseline: 1.0574x; 1.0034x over previous
#include <cuda_runtime.h>
#include <cuda_bf16.h>
#include <math.h>
#include <stdint.h>

#define NNODES 32768
#define NBATCH 16
#define NS 2048
#define HID 64
#define ETOT 524288
#define EPSF 1e-5f

// ---------------- scratch ----------------
__device__ float g_h[NNODES * HID];
__device__ float g_agg[NNODES * HID];
__device__ float g_u[NNODES * HID];
__device__ float g_PQ[NNODES * 128];   // P = h@W1top + b1 (cols 0-63), Q = h@W1bot (cols 64-127)
__device__ float g_X[NNODES * 3];
__device__ float g_Y[64 * 3];
__device__ float g_acc[2 * NBATCH];

// ---------------- node-MLP smem (weights only) ----------------
#define B1_HI  0
#define B1_LO  17408
#define B2_HI  34816
#define B2_LO  44032
#define BIAS1  53248
#define BIAS2  53504
#define SMEM_MMA_BYTES 53760

// ---------------- edge smem: B2 only ----------------
#define E_B2_HI  0
#define E_B2_LO  9216
#define E_BIAS2  18432
#define SMEM_EDGE_BYTES 18688

// ---------------- precompute smem: B1^T [128n][72k] ----------------
#define P_B1_HI  0
#define P_B1_LO  18432
#define P_BIAS1  36864
#define SMEM_PRE_BYTES 37120

static __device__ __forceinline__ uint32_t cvta_smem(const void* p) {
    uint32_t a;
    asm("{ .reg .u64 t; cvta.to.shared.u64 t, %1; cvt.u32.u64 %0, t; }" : "=r"(a) : "l"(p));
    return a;
}
static __device__ __forceinline__ void ldsm4(uint32_t* r, uint32_t addr) {
    asm volatile("ldmatrix.sync.aligned.m8n8.x4.shared.b16 {%0,%1,%2,%3}, [%4];"
                 : "=r"(r[0]), "=r"(r[1]), "=r"(r[2]), "=r"(r[3]) : "r"(addr));
}
static __device__ __forceinline__ void mma_bf16(float* c, const uint32_t* a, const uint32_t* b) {
    asm volatile(
        "mma.sync.aligned.m16n8k16.row.col.f32.bf16.bf16.f32 "
        "{%0,%1,%2,%3}, {%4,%5,%6,%7}, {%8,%9}, {%0,%1,%2,%3};"
        : "+f"(c[0]), "+f"(c[1]), "+f"(c[2]), "+f"(c[3])
        : "r"(a[0]), "r"(a[1]), "r"(a[2]), "r"(a[3]), "r"(b[0]), "r"(b[1]));
}
static __device__ __forceinline__ void split2(float x, float y, uint32_t& hi, uint32_t& lo) {
    __nv_bfloat16 hx = __float2bfloat16(x), hy = __float2bfloat16(y);
    __nv_bfloat16 lx = __float2bfloat16(x - __bfloat162float(hx));
    __nv_bfloat16 ly = __float2bfloat16(y - __bfloat162float(hy));
    hi = ((uint32_t)__bfloat16_as_ushort(hy) << 16) | (uint32_t)__bfloat16_as_ushort(hx);
    lo = ((uint32_t)__bfloat16_as_ushort(ly) << 16) | (uint32_t)__bfloat16_as_ushort(lx);
}

// fast exp, FFMA-only
__device__ __forceinline__ float fexp(float x) {
    const float L2E = 1.4426950408889634f;
    float t = fmaf(x, L2E, 12582912.0f);
    float kf = t - 12582912.0f;
    float f = fmaf(x, L2E, -kf);
    float p = 1.33335581e-3f;
    p = fmaf(p, f, 9.61812911e-3f);
    p = fmaf(p, f, 5.55041087e-2f);
    p = fmaf(p, f, 2.40226507e-1f);
    p = fmaf(p, f, 6.93147181e-1f);
    p = fmaf(p, f, 1.0f);
    int ik = (int)kf;
    return __int_as_float(__float_as_int(p) + (ik << 23));
}

__global__ void compute_Y_kernel() {
    int i = threadIdx.x;
    if (i < 64) {
        double phi = 3.14159265358979323846 * (3.0 - sqrt(5.0));
        double y = 1.0 - 2.0 * (double)i / 63.0;
        double r = sqrt(fmax(0.0, 1.0 - y * y));
        double th = phi * (double)i;
        g_Y[i * 3 + 0] = (float)(cos(th) * r);
        g_Y[i * 3 + 1] = (float)y;
        g_Y[i * 3 + 2] = (float)(sin(th) * r);
    }
}

__global__ void zero_acc_kernel() {
    int i = threadIdx.x;
    if (i < 2 * NBATCH) g_acc[i] = 0.f;
}

__global__ void encoder_kernel(const float* __restrict__ x,
                               const float* __restrict__ W,
                               const float* __restrict__ b) {
    __shared__ float sW[3 * HID];
    __shared__ float sb[HID];
    int t = threadIdx.x;
    if (t < 3 * HID) sW[t] = W[t];
    if (t < HID) sb[t] = b[t];
    __syncthreads();
    int idx = blockIdx.x * 256 + t;
    int n = idx >> 6, c = idx & 63;
    float x0 = x[n * 3 + 0], x1 = x[n * 3 + 1], x2 = x[n * 3 + 2];
    g_h[idx] = fmaf(x0, sW[c], fmaf(x1, sW[HID + c], fmaf(x2, sW[2 * HID + c], sb[c])));
}

// ============ precompute: PQ = h @ [W1top | W1bot] (+b1 on P half); also zeroes g_agg ============
// 128 threads (4 warps), warp = m16 x n64 per half, 64 rows/tile, 512 tiles, 4 CTAs/SM.
__global__ void __launch_bounds__(128, 4) precompute_kernel(
    const float* __restrict__ W1g, const float* __restrict__ b1g) {
    extern __shared__ char sp[];
    const uint32_t sb = cvta_smem(sp);
    const int t = threadIdx.x, lane = t & 31, wid = t >> 5;
    float* b1v = reinterpret_cast<float*>(sp + P_BIAS1);

    // zero g_agg (replaces zero_agg kernel)
    {
        float4 z = make_float4(0.f, 0.f, 0.f, 0.f);
        float4* az = reinterpret_cast<float4*>(g_agg);
        for (int i = blockIdx.x * 128 + t; i < NNODES * HID / 4; i += gridDim.x * 128)
            az[i] = z;
    }

    // B1^T [128 n][72 k pad]: rows 0-63 = W1top^T (P), rows 64-127 = W1bot^T (Q)
    for (int i = t; i < 128 * 64; i += 128) {
        int k = i >> 6, n = i & 63;
        float w = W1g[i];
        __nv_bfloat16 hi = __float2bfloat16(w);
        __nv_bfloat16 lo = __float2bfloat16(w - __bfloat162float(hi));
        int nn = (k < 64) ? n : (64 + n);
        int k2 = k & 63;
        reinterpret_cast<__nv_bfloat16*>(sp + P_B1_HI)[nn * 72 + k2] = hi;
        reinterpret_cast<__nv_bfloat16*>(sp + P_B1_LO)[nn * 72 + k2] = lo;
    }
    if (t < 64) b1v[t] = b1g[t];
    __syncthreads();

    const int g = lane >> 3;
    const int b_row = (g >> 1) * 8 + (lane & 7);
    const int b_koff = (g & 1) * 8;
    const int er = lane >> 2, ec = lane & 3;
    const int m0 = wid * 16;
    const uint32_t aB = sb + P_B1_HI + (uint32_t)b_row * 144 + b_koff * 2;

    for (int tile = blockIdx.x; tile < NNODES / 64; tile += gridDim.x) {
        const int r0 = tile * 64 + m0 + er, r1 = r0 + 8;
        const float* ha = g_h + (size_t)r0 * HID;
        const float* hb = g_h + (size_t)r1 * HID;
        uint32_t ah[4][4], al[4][4];
        #pragma unroll
        for (int kk = 0; kk < 4; kk++) {
            int cb = kk * 16 + 2 * ec;
            float2 p0 = *reinterpret_cast<const float2*>(ha + cb);
            float2 p1 = *reinterpret_cast<const float2*>(hb + cb);
            float2 p2 = *reinterpret_cast<const float2*>(ha + cb + 8);
            float2 p3 = *reinterpret_cast<const float2*>(hb + cb + 8);
            split2(p0.x, p0.y, ah[kk][0], al[kk][0]);
            split2(p1.x, p1.y, ah[kk][1], al[kk][1]);
            split2(p2.x, p2.y, ah[kk][2], al[kk][2]);
            split2(p3.x, p3.y, ah[kk][3], al[kk][3]);
        }
        #pragma unroll
        for (int half = 0; half < 2; half++) {
            float acc[8][4];
            #pragma unroll
            for (int nt = 0; nt < 8; nt++)
                #pragma unroll
                for (int j = 0; j < 4; j++) acc[nt][j] = 0.f;
            #pragma unroll
            for (int kk = 0; kk < 4; kk++) {
                uint32_t bh[4][4], bl[4][4];
                #pragma unroll
                for (int i = 0; i < 4; i++) {
                    uint32_t a = aB + (uint32_t)(half * 64 + i * 16) * 144 + kk * 32;
                    ldsm4(bh[i], a);
                    ldsm4(bl[i], a + 18432);
                }
                #pragma unroll
                for (int nt = 0; nt < 8; nt++) {
                    const uint32_t* bhp = &bh[nt >> 1][(nt & 1) * 2];
                    const uint32_t* blp = &bl[nt >> 1][(nt & 1) * 2];
                    mma_bf16(acc[nt], ah[kk], bhp);
                    mma_bf16(acc[nt], al[kk], bhp);
                    mma_bf16(acc[nt], ah[kk], blp);
                }
            }
            float* o0 = g_PQ + (size_t)r0 * 128 + half * 64;
            float* o1 = g_PQ + (size_t)r1 * 128 + half * 64;
            #pragma unroll
            for (int nt = 0; nt < 8; nt++) {
                int n = 8 * nt + 2 * ec;
                float bx = half ? 0.f : b1v[n];
                float by = half ? 0.f : b1v[n + 1];
                *reinterpret_cast<float2*>(o0 + n) = make_float2(acc[nt][0] + bx, acc[nt][1] + by);
                *reinterpret_cast<float2*>(o1 + n) = make_float2(acc[nt][2] + bx, acc[nt][3] + by);
            }
        }
    }
}

// ============ edge: Mid = relu(P[dst]+Q[src]); agg[dst] += relu(Mid@W2+b2) ============
__global__ void __launch_bounds__(128, 4) edge_pq_kernel(
    const float* __restrict__ W2g, const float* __restrict__ b2g,
    const int* __restrict__ esrc, const int* __restrict__ edst) {
    extern __shared__ char sp[];
    const uint32_t sb = cvta_smem(sp);
    const int t = threadIdx.x, lane = t & 31, wid = t >> 5;
    float* b2v = reinterpret_cast<float*>(sp + E_BIAS2);

    for (int i = t; i < 64 * 64; i += 128) {
        int k = i >> 6, n = i & 63;
        float w = W2g[i];
        __nv_bfloat16 hi = __float2bfloat16(w);
        __nv_bfloat16 lo = __float2bfloat16(w - __bfloat162float(hi));
        reinterpret_cast<__nv_bfloat16*>(sp + E_B2_HI)[n * 72 + k] = hi;
        reinterpret_cast<__nv_bfloat16*>(sp + E_B2_LO)[n * 72 + k] = lo;
    }
    if (t < 64) b2v[t] = b2g[t];
    __syncthreads();

    const int g = lane >> 3;
    const int b_row = (g >> 1) * 8 + (lane & 7);
    const int b_koff = (g & 1) * 8;
    const int er = lane >> 2, ec = lane & 3;
    const int m0 = wid * 32;
    const uint32_t aB2 = sb + E_B2_HI + (uint32_t)b_row * 144 + b_koff * 2;

    for (int tile = blockIdx.x; tile < ETOT / 128; tile += gridDim.x) {
        const int base = tile * 128;
        int dd[4], ss[4];
        #pragma unroll
        for (int i = 0; i < 4; i++) {
            int r = base + m0 + 8 * i + er;
            dd[i] = edst[r];
            ss[i] = esrc[r];
        }
        #pragma unroll
        for (int mt = 0; mt < 2; mt++) {
            const float* P0 = g_PQ + (size_t)dd[2 * mt] * 128;
            const float* P1 = g_PQ + (size_t)dd[2 * mt + 1] * 128;
            const float* Q0 = g_PQ + (size_t)ss[2 * mt] * 128 + 64;
            const float* Q1 = g_PQ + (size_t)ss[2 * mt + 1] * 128 + 64;
            uint32_t fh[4][4], fl[4][4];
            #pragma unroll
            for (int kk = 0; kk < 4; kk++) {
                int cb = kk * 16 + 2 * ec;
                float2 pa = *reinterpret_cast<const float2*>(P0 + cb);
                float2 qa = *reinterpret_cast<const float2*>(Q0 + cb);
                float2 pb = *reinterpret_cast<const float2*>(P1 + cb);
                float2 qb = *reinterpret_cast<const float2*>(Q1 + cb);
                float2 pc = *reinterpret_cast<const float2*>(P0 + cb + 8);
                float2 qc = *reinterpret_cast<const float2*>(Q0 + cb + 8);
                float2 pd = *reinterpret_cast<const float2*>(P1 + cb + 8);
                float2 qd = *reinterpret_cast<const float2*>(Q1 + cb + 8);
                split2(fmaxf(pa.x + qa.x, 0.f), fmaxf(pa.y + qa.y, 0.f), fh[kk][0], fl[kk][0]);
                split2(fmaxf(pb.x + qb.x, 0.f), fmaxf(pb.y + qb.y, 0.f), fh[kk][1], fl[kk][1]);
                split2(fmaxf(pc.x + qc.x, 0.f), fmaxf(pc.y + qc.y, 0.f), fh[kk][2], fl[kk][2]);
                split2(fmaxf(pd.x + qd.x, 0.f), fmaxf(pd.y + qd.y, 0.f), fh[kk][3], fl[kk][3]);
            }
            float acc2[8][4];
            #pragma unroll
            for (int nt = 0; nt < 8; nt++)
                #pragma unroll
                for (int j = 0; j < 4; j++) acc2[nt][j] = 0.f;
            #pragma unroll
            for (int kk = 0; kk < 4; kk++) {
                uint32_t bh[4][4], bl[4][4];
                #pragma unroll
                for (int i = 0; i < 4; i++) {
                    uint32_t a = aB2 + (uint32_t)i * 16 * 144 + kk * 32;
                    ldsm4(bh[i], a);
                    ldsm4(bl[i], a + 9216);
                }
                #pragma unroll
                for (int nt = 0; nt < 8; nt++) {
                    const uint32_t* bhp = &bh[nt >> 1][(nt & 1) * 2];
                    const uint32_t* blp = &bl[nt >> 1][(nt & 1) * 2];
                    mma_bf16(acc2[nt], fh[kk], bhp);
                    mma_bf16(acc2[nt], fl[kk], bhp);
                    mma_bf16(acc2[nt], fh[kk], blp);
                }
            }
            #pragma unroll
            for (int nt = 0; nt < 8; nt++) {
                int n = 8 * nt + 2 * ec;
                float2 bb = *reinterpret_cast<const float2*>(b2v + n);
                float v00 = fmaxf(acc2[nt][0] + bb.x, 0.f);
                float v01 = fmaxf(acc2[nt][1] + bb.y, 0.f);
                float v10 = fmaxf(acc2[nt][2] + bb.x, 0.f);
                float v11 = fmaxf(acc2[nt][3] + bb.y, 0.f);
                float* p0 = g_agg + (size_t)dd[2 * mt] * HID + n;
                float* p1 = g_agg + (size_t)dd[2 * mt + 1] * HID + n;
                asm volatile("red.global.add.v2.f32 [%0], {%1,%2};"
                             :: "l"(p0), "f"(v00), "f"(v01) : "memory");
                asm volatile("red.global.add.v2.f32 [%0], {%1,%2};"
                             :: "l"(p1), "f"(v10), "f"(v11) : "memory");
            }
        }
    }
}

// ============ node MLP ============
__global__ void __launch_bounds__(128, 3) node_mma_kernel(
    const float* __restrict__ W1g, const float* __restrict__ b1g,
    const float* __restrict__ W2g, const float* __restrict__ b2g) {
    extern __shared__ char sp[];
    const uint32_t sb = cvta_smem(sp);
    const int t = threadIdx.x, lane = t & 31, wid = t >> 5;

    float* b1v = reinterpret_cast<float*>(sp + BIAS1);
    float* b2v = reinterpret_cast<float*>(sp + BIAS2);

    for (int i = t; i < 128 * 64; i += 128) {
        int k = i >> 6, n = i & 63;
        float w = W1g[i];
        __nv_bfloat16 hi = __float2bfloat16(w);
        __nv_bfloat16 lo = __float2bfloat16(w - __bfloat162float(hi));
        reinterpret_cast<__nv_bfloat16*>(sp + B1_HI)[n * 136 + k] = hi;
        reinterpret_cast<__nv_bfloat16*>(sp + B1_LO)[n * 136 + k] = lo;
    }
    for (int i = t; i < 64 * 64; i += 128) {
        int k = i >> 6, n = i & 63;
        float w = W2g[i];
        __nv_bfloat16 hi = __float2bfloat16(w);
        __nv_bfloat16 lo = __float2bfloat16(w - __bfloat162float(hi));
        reinterpret_cast<__nv_bfloat16*>(sp + B2_HI)[n * 72 + k] = hi;
        reinterpret_cast<__nv_bfloat16*>(sp + B2_LO)[n * 72 + k] = lo;
    }
    if (t < 64) { b1v[t] = b1g[t]; b2v[t] = b2g[t]; }
    __syncthreads();

    const int g = lane >> 3;
    const int b_row = (g >> 1) * 8 + (lane & 7);
    const int b_koff = (g & 1) * 8;
    const int er = lane >> 2, ec = lane & 3;
    const int m0 = wid * 32;

    const uint32_t aB1 = sb + B1_HI + (uint32_t)b_row * 272 + b_koff * 2;
    const uint32_t aB2 = sb + B2_HI + (uint32_t)b_row * 144 + b_koff * 2;

    for (int tile = blockIdx.x; tile < NNODES / 128; tile += gridDim.x) {
        const int base = tile * 128;
        int rr[4];
        #pragma unroll
        for (int i = 0; i < 4; i++) rr[i] = base + m0 + 8 * i + er;

        float acc1[2][8][4];
        #pragma unroll
        for (int mt = 0; mt < 2; mt++)
            #pragma unroll
            for (int nt = 0; nt < 8; nt++)
                #pragma unroll
                for (int j = 0; j < 4; j++) acc1[mt][nt][j] = 0.f;
        #pragma unroll
        for (int kk = 0; kk < 8; kk++) {
            const int kb = (kk & 3) * 16;
            uint32_t ah[2][4], al[2][4];
            #pragma unroll
            for (int mt = 0; mt < 2; mt++) {
                const float* src = (kk < 4) ? g_h : g_agg;
                const float* qa = src + (size_t)rr[2 * mt] * HID;
                const float* qb = src + (size_t)rr[2 * mt + 1] * HID;
                float2 p0 = *reinterpret_cast<const float2*>(qa + kb + 2 * ec);
                float2 p1 = *reinterpret_cast<const float2*>(qb + kb + 2 * ec);
                float2 p2 = *reinterpret_cast<const float2*>(qa + kb + 8 + 2 * ec);
                float2 p3 = *reinterpret_cast<const float2*>(qb + kb + 8 + 2 * ec);
                split2(p0.x, p0.y, ah[mt][0], al[mt][0]);
                split2(p1.x, p1.y, ah[mt][1], al[mt][1]);
                split2(p2.x, p2.y, ah[mt][2], al[mt][2]);
                split2(p3.x, p3.y, ah[mt][3], al[mt][3]);
            }
            uint32_t bh[4][4], bl[4][4];
            #pragma unroll
            for (int i = 0; i < 4; i++) {
                uint32_t a = aB1 + (uint32_t)i * 16 * 272 + kk * 32;
                ldsm4(bh[i], a);
                ldsm4(bl[i], a + 17408);
            }
            #pragma unroll
            for (int mt = 0; mt < 2; mt++)
                #pragma unroll
                for (int nt = 0; nt < 8; nt++) {
                    const uint32_t* bhp = &bh[nt >> 1][(nt & 1) * 2];
                    const uint32_t* blp = &bl[nt >> 1][(nt & 1) * 2];
                    mma_bf16(acc1[mt][nt], ah[mt], bhp);
                    mma_bf16(acc1[mt][nt], al[mt], bhp);
                    mma_bf16(acc1[mt][nt], ah[mt], blp);
                }
        }
        uint32_t fh[2][4][4], fl[2][4][4];
        #pragma unroll
        for (int mt = 0; mt < 2; mt++)
            #pragma unroll
            for (int j = 0; j < 4; j++) {
                float2 ba = *reinterpret_cast<const float2*>(b1v + 16 * j + 2 * ec);
                float2 bb = *reinterpret_cast<const float2*>(b1v + 16 * j + 8 + 2 * ec);
                float v00 = fmaxf(acc1[mt][2 * j][0] + ba.x, 0.f);
                float v01 = fmaxf(acc1[mt][2 * j][1] + ba.y, 0.f);
                float v10 = fmaxf(acc1[mt][2 * j][2] + ba.x, 0.f);
                float v11 = fmaxf(acc1[mt][2 * j][3] + ba.y, 0.f);
                float w00 = fmaxf(acc1[mt][2 * j + 1][0] + bb.x, 0.f);
                float w01 = fmaxf(acc1[mt][2 * j + 1][1] + bb.y, 0.f);
                float w10 = fmaxf(acc1[mt][2 * j + 1][2] + bb.x, 0.f);
                float w11 = fmaxf(acc1[mt][2 * j + 1][3] + bb.y, 0.f);
                split2(v00, v01, fh[mt][j][0], fl[mt][j][0]);
                split2(v10, v11, fh[mt][j][1], fl[mt][j][1]);
                split2(w00, w01, fh[mt][j][2], fl[mt][j][2]);
                split2(w10, w11, fh[mt][j][3], fl[mt][j][3]);
            }
        float acc2[2][8][4];
        #pragma unroll
        for (int mt = 0; mt < 2; mt++)
            #pragma unroll
            for (int nt = 0; nt < 8; nt++)
                #pragma unroll
                for (int j = 0; j < 4; j++) acc2[mt][nt][j] = 0.f;
        #pragma unroll
        for (int kk = 0; kk < 4; kk++) {
            uint32_t bh[4][4], bl[4][4];
            #pragma unroll
            for (int i = 0; i < 4; i++) {
                uint32_t a = aB2 + (uint32_t)i * 16 * 144 + kk * 32;
                ldsm4(bh[i], a);
                ldsm4(bl[i], a + 9216);
            }
            #pragma unroll
            for (int mt = 0; mt < 2; mt++)
                #pragma unroll
                for (int nt = 0; nt < 8; nt++) {
                    const uint32_t* bhp = &bh[nt >> 1][(nt & 1) * 2];
                    const uint32_t* blp = &bl[nt >> 1][(nt & 1) * 2];
                    mma_bf16(acc2[mt][nt], fh[mt][kk], bhp);
                    mma_bf16(acc2[mt][nt], fl[mt][kk], bhp);
                    mma_bf16(acc2[mt][nt], fh[mt][kk], blp);
                }
        }
        #pragma unroll
        for (int mt = 0; mt < 2; mt++)
            #pragma unroll
            for (int nt = 0; nt < 8; nt++) {
                int n = 8 * nt + 2 * ec;
                float2 bb = *reinterpret_cast<const float2*>(b2v + n);
                float v00 = fmaxf(acc2[mt][nt][0] + bb.x, 0.f);
                float v01 = fmaxf(acc2[mt][nt][1] + bb.y, 0.f);
                float v10 = fmaxf(acc2[mt][nt][2] + bb.x, 0.f);
                float v11 = fmaxf(acc2[mt][nt][3] + bb.y, 0.f);
                *reinterpret_cast<float2*>(g_u + (size_t)rr[2 * mt] * HID + n) =
                    make_float2(v00, v01);
                *reinterpret_cast<float2*>(g_u + (size_t)rr[2 * mt + 1] * HID + n) =
                    make_float2(v10, v11);
            }
    }
}

// ---------------- InstanceNorm: 64 blocks = (graph, 16-ch quad) ----------------
__global__ void instnorm_kernel() {
    int g = blockIdx.x >> 2, cq = (blockIdx.x & 3) << 4;
    int t = threadIdx.x;          // 512
    int c = t & 15, r = t >> 4;   // r 0..31
    const float* basep = g_u + (size_t)g * NS * HID + cq + c;
    float* outp = g_h + (size_t)g * NS * HID + cq + c;
    __shared__ float red[32][16];
    float s = 0.f;
    for (int n = r; n < NS; n += 32) s += basep[(size_t)n * HID];
    red[r][c] = s;
    __syncthreads();
    if (r == 0) {
        float tot = 0.f;
        #pragma unroll
        for (int i = 0; i < 32; i++) tot += red[i][c];
        red[0][c] = tot * (1.0f / NS);
    }
    __syncthreads();
    float mean = red[0][c];
    __syncthreads();
    float s2 = 0.f;
    for (int n = r; n < NS; n += 32) {
        float d = basep[(size_t)n * HID] - mean;
        s2 = fmaf(d, d, s2);
    }
    red[r][c] = s2;
    __syncthreads();
    if (r == 0) {
        float tot = 0.f;
        #pragma unroll
        for (int i = 0; i < 32; i++) tot += red[i][c];
        red[0][c] = rsqrtf(tot * (1.0f / NS) + EPSF);
    }
    __syncthreads();
    float inv = red[0][c];
    for (int n = r; n < NS; n += 32)
        outp[(size_t)n * HID] = (basep[(size_t)n * HID] - mean) * inv;
}

// ---------------- decoder ----------------
__global__ void decoder_kernel(const float* __restrict__ W, const float* __restrict__ b,
                               float* __restrict__ out) {
    __shared__ float sW[HID * 3];
    __shared__ float sb[3];
    int t = threadIdx.x;
    if (t < HID * 3) sW[t] = W[t];
    if (t < 3) sb[t] = b[t];
    __syncthreads();
    int n = blockIdx.x * 256 + t;
    float a0 = sb[0], a1 = sb[1], a2 = sb[2];
    const float* hr = g_h + (size_t)n * HID;
    #pragma unroll 8
    for (int k = 0; k < HID; k++) {
        float v = hr[k];
        a0 = fmaf(v, sW[k * 3 + 0], a0);
        a1 = fmaf(v, sW[k * 3 + 1], a1);
        a2 = fmaf(v, sW[k * 3 + 2], a2);
    }
    float inv = rsqrtf(a0 * a0 + a1 * a1 + a2 * a2);
    a0 *= inv; a1 *= inv; a2 *= inv;
    g_X[n * 3 + 0] = a0; g_X[n * 3 + 1] = a1; g_X[n * 3 + 2] = a2;
    out[1 + n * 3 + 0] = a0; out[1 + n * 3 + 1] = a1; out[1 + n * 3 + 2] = a2;
}

// ---------------- MMD: kXX symmetric (tm<=tn blocks, off-diag weighted x2) ----------------
__global__ void kxx_kernel() {
    int bid = blockIdx.x;                 // NBATCH * 136
    int g = bid / 136, p = bid - g * 136;
    int tm = 0, rem = p;
    while (rem >= 16 - tm) { rem -= 16 - tm; tm++; }
    int tn = tm + rem;
    float wgt = (tm == tn) ? 1.f : 2.f;
    const float* Xg = g_X + (size_t)g * NS * 3;
    __shared__ float ax[128][4];
    __shared__ float ay[128][4];
    __shared__ float rs[256];
    int t = threadIdx.x;
    for (int i = t; i < 128 * 3; i += 256) {
        int row = i / 3, col = i - row * 3;
        ax[row][col] = Xg[tm * 128 * 3 + i];
        ay[row][col] = Xg[tn * 128 * 3 + i];
    }
    __syncthreads();
    int r0 = (t >> 4) << 3, cb = (t & 15) << 3;
    float yv[8][3];
    #pragma unroll
    for (int j = 0; j < 8; j++) {
        yv[j][0] = ay[cb + j][0]; yv[j][1] = ay[cb + j][1]; yv[j][2] = ay[cb + j][2];
    }
    float s = 0.f;
    #pragma unroll
    for (int i = 0; i < 8; i++) {
        float x0 = ax[r0 + i][0], x1 = ax[r0 + i][1], x2 = ax[r0 + i][2];
        #pragma unroll
        for (int j = 0; j < 8; j++) {
            float d = fmaf(x0, yv[j][0], fmaf(x1, yv[j][1], x2 * yv[j][2]));
            s += fexp(fmaf(2.f, d, -2.f));
        }
    }
    rs[t] = s;
    __syncthreads();
    for (int o = 128; o > 0; o >>= 1) { if (t < o) rs[t] += rs[t + o]; __syncthreads(); }
    if (t == 0) atomicAdd(&g_acc[g], rs[0] * wgt);
}

__global__ void kxy_kernel() {
    __shared__ float sy[64][4];
    __shared__ float rs[256];
    int t = threadIdx.x;
    int n = blockIdx.x * 256 + t;
    for (int i = t; i < 64 * 3; i += 256) { int row = i / 3; sy[row][i - row * 3] = g_Y[i]; }
    __syncthreads();
    float x0 = g_X[n * 3], x1 = g_X[n * 3 + 1], x2 = g_X[n * 3 + 2];
    float s = 0.f;
    #pragma unroll 8
    for (int j = 0; j < 64; j++) {
        float d = fmaf(x0, sy[j][0], fmaf(x1, sy[j][1], x2 * sy[j][2]));
        s += fexp(fmaf(2.f, d, -2.f));
    }
    rs[t] = s;
    __syncthreads();
    for (int o = 128; o > 0; o >>= 1) { if (t < o) rs[t] += rs[t + o]; __syncthreads(); }
    if (t == 0) atomicAdd(&g_acc[NBATCH + (n >> 11)], rs[0]);
}

__global__ void finalize_kernel(float* __restrict__ out) {
    __shared__ float rs[64];
    int t = threadIdx.x;
    float x0 = g_Y[t * 3], x1 = g_Y[t * 3 + 1], x2 = g_Y[t * 3 + 2];
    float s = 0.f;
    for (int j = 0; j < 64; j++) {
        float d = fmaf(x0, g_Y[j * 3], fmaf(x1, g_Y[j * 3 + 1], x2 * g_Y[j * 3 + 2]));
        s += fexp(fmaf(2.f, d, -2.f));
    }
    rs[t] = s;
    __syncthreads();
    if (t == 0) {
        float kyy = 0.f;
        for (int j = 0; j < 64; j++) kyy += rs[j];
        kyy *= (1.0f / (64.f * 64.f));
        float loss = 0.f;
        for (int b = 0; b < NBATCH; b++) {
            float kxx = g_acc[b] * (1.0f / ((float)NS * (float)NS));
            float kxy = g_acc[NBATCH + b] * (1.0f / ((float)NS * 64.f));
            loss += kxx - 2.f * kxy + kyy;
        }
        out[0] = loss * (1.0f / NBATCH);
    }
}

// ---------------- launch ----------------
extern "C" void kernel_launch(void* const* d_in, const int* in_sizes, int n_in,
                              void* d_out, int out_size) {
    const float* x    = (const float*)d_in[0];
    const int*   esrc = (const int*)d_in[1];
    const int*   edst = (const int*)d_in[2];
    const float* encW = (const float*)d_in[4];
    const float* encb = (const float*)d_in[5];
    const float* m1W  = (const float*)d_in[6];
    const float* m1b  = (const float*)d_in[7];
    const float* m2W  = (const float*)d_in[8];
    const float* m2b  = (const float*)d_in[9];
    const float* u1W  = (const float*)d_in[10];
    const float* u1b  = (const float*)d_in[11];
    const float* u2W  = (const float*)d_in[12];
    const float* u2b  = (const float*)d_in[13];
    const float* decW = (const float*)d_in[14];
    const float* decb = (const float*)d_in[15];
    float* out = (float*)d_out;

    cudaFuncSetAttribute((const void*)node_mma_kernel,
                         cudaFuncAttributeMaxDynamicSharedMemorySize, SMEM_MMA_BYTES);
    cudaFuncSetAttribute((const void*)precompute_kernel,
                         cudaFuncAttributeMaxDynamicSharedMemorySize, SMEM_PRE_BYTES);
    cudaFuncSetAttribute((const void*)edge_pq_kernel,
                         cudaFuncAttributeMaxDynamicSharedMemorySize, SMEM_EDGE_BYTES);

    compute_Y_kernel<<<1, 64>>>();
    encoder_kernel<<<NNODES * HID / 256, 256>>>(x, encW, encb);

    for (int l = 0; l < 4; l++) {
        precompute_kernel<<<512, 128, SMEM_PRE_BYTES>>>(
            m1W + (size_t)l * 128 * 64, m1b + (size_t)l * 64);
        edge_pq_kernel<<<592, 128, SMEM_EDGE_BYTES>>>(
            m2W + (size_t)l * 64 * 64, m2b + (size_t)l * 64, esrc, edst);
        node_mma_kernel<<<256, 128, SMEM_MMA_BYTES>>>(
            u1W + (size_t)l * 128 * 64, u1b + (size_t)l * 64,
            u2W + (size_t)l * 64 * 64,  u2b + (size_t)l * 64);
        instnorm_kernel<<<64, 512>>>();
    }

    zero_acc_kernel<<<1, 32>>>();
    decoder_kernel<<<NNODES / 256, 256>>>(decW, decb, out);
    kxy_kernel<<<NNODES / 256, 256>>>();
    kxx_kernel<<<NBATCH * 136, 256>>>();
    finalize_kernel<<<1, 64>>>(out);
}